// round 1
// baseline (speedup 1.0000x reference)
#include <cuda_runtime.h>
#include <math.h>

// ---------------------------------------------------------------------------
// Problem constants
// ---------------------------------------------------------------------------
#define N_NODES 50000
#define T_WIN   3
#define E_PER_T 100000
#define HID     128
#define NH      8
#define DK      16
#define M_ROWS  (T_WIN * N_NODES)          // 150000 rows for QKV GEMMs
#define N_PAIRS 6                          // (t_tar,t_src) with t_src<=t_tar

// ---------------------------------------------------------------------------
// Device scratch (static globals -- no allocation allowed)
// ---------------------------------------------------------------------------
__device__ float    g_q[(size_t)M_ROWS * HID];
__device__ float    g_k[(size_t)M_ROWS * HID];
__device__ float    g_v[(size_t)M_ROWS * HID];
__device__ float    g_att[(size_t)N_PAIRS * E_PER_T * NH];
__device__ unsigned g_mmax[(size_t)T_WIN * N_NODES * NH];
__device__ unsigned g_mmin[(size_t)T_WIN * N_NODES * NH];
__device__ float    g_sc[(size_t)T_WIN * N_NODES * NH];
__device__ float    g_ss[(size_t)T_WIN * N_NODES * NH];
__device__ float    g_accc[(size_t)T_WIN * N_NODES * HID];
__device__ float    g_accs[(size_t)T_WIN * N_NODES * HID];

// ---------------------------------------------------------------------------
// Ordered-uint encoding for float atomicMax/atomicMin
// ---------------------------------------------------------------------------
__device__ __forceinline__ unsigned enc_f(float f) {
    unsigned u = __float_as_uint(f);
    return (u & 0x80000000u) ? ~u : (u | 0x80000000u);
}
__device__ __forceinline__ float dec_f(unsigned e) {
    return (e & 0x80000000u) ? __uint_as_float(e & 0x7FFFFFFFu)
                             : __uint_as_float(~e);
}

// ---------------------------------------------------------------------------
// K_clear: zero accumulators, init max/min encodings
// ---------------------------------------------------------------------------
__global__ void clear_kernel() {
    const size_t LEN_BIG = (size_t)T_WIN * N_NODES * HID;   // 19.2M
    const size_t LEN_SM  = (size_t)T_WIN * N_NODES * NH;    // 1.2M
    size_t i      = (size_t)blockIdx.x * blockDim.x + threadIdx.x;
    size_t stride = (size_t)gridDim.x * blockDim.x;
    for (size_t k = i; k < LEN_BIG; k += stride) {
        g_accc[k] = 0.0f;
        g_accs[k] = 0.0f;
    }
    for (size_t k = i; k < LEN_SM; k += stride) {
        g_sc[k]   = 0.0f;
        g_ss[k]   = 0.0f;
        g_mmax[k] = 0u;            // below any encoded float
        g_mmin[k] = 0xFFFFFFFFu;   // above any encoded float
    }
}

// ---------------------------------------------------------------------------
// K_qkv: C[m, 0:128] = X[m, 0:128] @ W + b  for W in {Wq, Wk, Wv}
// BM=64, BN=128, BK=32, 256 threads, per-thread tile 4x8
// ---------------------------------------------------------------------------
__global__ void qkv_kernel(const float* __restrict__ x,
                           const float* __restrict__ Wq, const float* __restrict__ bq,
                           const float* __restrict__ Wk, const float* __restrict__ bk,
                           const float* __restrict__ Wv, const float* __restrict__ bv) {
    const float* W; const float* b; float* out;
    if (blockIdx.y == 0)      { W = Wq; b = bq; out = g_q; }
    else if (blockIdx.y == 1) { W = Wk; b = bk; out = g_k; }
    else                      { W = Wv; b = bv; out = g_v; }

    __shared__ float Xs[64][33];
    __shared__ float Ws[32][128];

    const int tid  = threadIdx.x;
    const int m0   = blockIdx.x * 64;
    const int ty   = tid >> 4;            // 0..15
    const int tx   = tid & 15;            // 0..15
    const int row0 = ty * 4;
    const int col0 = tx * 8;

    float acc[4][8];
    #pragma unroll
    for (int i = 0; i < 4; i++)
        #pragma unroll
        for (int j = 0; j < 8; j++) acc[i][j] = 0.0f;

    for (int kc = 0; kc < 128; kc += 32) {
        // stage X tile 64x32 (512 float4 loads over 256 threads)
        #pragma unroll
        for (int l = 0; l < 2; l++) {
            int f4 = tid + l * 256;       // 0..511
            int r  = f4 >> 3;
            int c4 = f4 & 7;
            int grow = m0 + r;
            float4 val = make_float4(0.f, 0.f, 0.f, 0.f);
            if (grow < M_ROWS)
                val = *(const float4*)&x[(size_t)grow * HID + kc + c4 * 4];
            Xs[r][c4 * 4 + 0] = val.x;
            Xs[r][c4 * 4 + 1] = val.y;
            Xs[r][c4 * 4 + 2] = val.z;
            Xs[r][c4 * 4 + 3] = val.w;
        }
        // stage W tile 32x128 (1024 float4 loads)
        #pragma unroll
        for (int l = 0; l < 4; l++) {
            int f4 = tid + l * 256;       // 0..1023
            int r  = f4 >> 5;
            int c4 = f4 & 31;
            *(float4*)&Ws[r][c4 * 4] =
                *(const float4*)&W[(size_t)(kc + r) * HID + c4 * 4];
        }
        __syncthreads();

        #pragma unroll
        for (int k = 0; k < 32; k++) {
            float a[4], bb[8];
            #pragma unroll
            for (int i = 0; i < 4; i++) a[i] = Xs[row0 + i][k];
            #pragma unroll
            for (int j = 0; j < 8; j++) bb[j] = Ws[k][col0 + j];
            #pragma unroll
            for (int i = 0; i < 4; i++)
                #pragma unroll
                for (int j = 0; j < 8; j++)
                    acc[i][j] = fmaf(a[i], bb[j], acc[i][j]);
        }
        __syncthreads();
    }

    #pragma unroll
    for (int i = 0; i < 4; i++) {
        int grow = m0 + row0 + i;
        if (grow < M_ROWS) {
            #pragma unroll
            for (int j = 0; j < 8; j++)
                out[(size_t)grow * HID + col0 + j] = acc[i][j] + b[col0 + j];
        }
    }
}

// ---------------------------------------------------------------------------
// K_att: per (pair, edge, head) compute attention logit, atomic max/min per
// target node. 8 lanes per edge (one head each), 32 edges per block.
// ---------------------------------------------------------------------------
__global__ void edge_att_kernel(const int* __restrict__ ei) {
    const int tt[N_PAIRS] = {0, 1, 1, 2, 2, 2};
    const int ts[N_PAIRS] = {0, 0, 1, 0, 1, 2};
    const int p     = blockIdx.y;
    const int t_tar = tt[p];
    const int t_src = ts[p];

    int e = blockIdx.x * 32 + (threadIdx.x >> 3);
    int h = threadIdx.x & 7;
    if (e >= E_PER_T) return;

    int src = ei[(size_t)t_src * 2 * E_PER_T + e];
    int tar = ei[(size_t)t_src * 2 * E_PER_T + E_PER_T + e];

    const float4* qp = (const float4*)(g_q + ((size_t)t_tar * N_NODES + tar) * HID + h * DK);
    const float4* kp = (const float4*)(g_k + ((size_t)t_src * N_NODES + src) * HID + h * DK);
    float a = 0.0f;
    #pragma unroll
    for (int i = 0; i < 4; i++) {
        float4 qv = qp[i];
        float4 kv = kp[i];
        a += qv.x * kv.x + qv.y * kv.y + qv.z * kv.z + qv.w * kv.w;
    }
    a *= 0.25f;   // 1/sqrt(DK), DK=16

    g_att[((size_t)p * E_PER_T + e) * NH + h] = a;

    size_t mh = ((size_t)t_tar * N_NODES + tar) * NH + h;
    unsigned ea = enc_f(a);
    atomicMax(&g_mmax[mh], ea);
    atomicMin(&g_mmin[mh], ea);
}

// ---------------------------------------------------------------------------
// K_scatter: ex = exp(att - max), exs = exp(min - att); accumulate
// s_c/s_s and ex-weighted v into per-node accumulators via atomics.
// ---------------------------------------------------------------------------
__global__ void edge_scatter_kernel(const int* __restrict__ ei) {
    const int tt[N_PAIRS] = {0, 1, 1, 2, 2, 2};
    const int ts[N_PAIRS] = {0, 0, 1, 0, 1, 2};
    const int p     = blockIdx.y;
    const int t_tar = tt[p];
    const int t_src = ts[p];

    int e = blockIdx.x * 32 + (threadIdx.x >> 3);
    int h = threadIdx.x & 7;
    if (e >= E_PER_T) return;

    int src = ei[(size_t)t_src * 2 * E_PER_T + e];
    int tar = ei[(size_t)t_src * 2 * E_PER_T + E_PER_T + e];

    float a = g_att[((size_t)p * E_PER_T + e) * NH + h];

    size_t mh = ((size_t)t_tar * N_NODES + tar) * NH + h;
    float Mx = dec_f(g_mmax[mh]);
    float Mn = dec_f(g_mmin[mh]);
    float ec = expf(a - Mx);
    float es = expf(Mn - a);

    atomicAdd(&g_sc[mh], ec);
    atomicAdd(&g_ss[mh], es);

    const float4* vp = (const float4*)(g_v + ((size_t)t_src * N_NODES + src) * HID + h * DK);
    float* pc = &g_accc[((size_t)t_tar * N_NODES + tar) * HID + h * DK];
    float* ps = &g_accs[((size_t)t_tar * N_NODES + tar) * HID + h * DK];
    #pragma unroll
    for (int q4 = 0; q4 < 4; q4++) {
        float4 v = vp[q4];
        atomicAdd(&pc[q4 * 4 + 0], ec * v.x);
        atomicAdd(&pc[q4 * 4 + 1], ec * v.y);
        atomicAdd(&pc[q4 * 4 + 2], ec * v.z);
        atomicAdd(&pc[q4 * 4 + 3], ec * v.w);
        atomicAdd(&ps[q4 * 4 + 0], es * v.x);
        atomicAdd(&ps[q4 * 4 + 1], es * v.y);
        atomicAdd(&ps[q4 * 4 + 2], es * v.z);
        atomicAdd(&ps[q4 * 4 + 3], es * v.w);
    }
}

// ---------------------------------------------------------------------------
// Warp-cooperative FFN: LayerNorm -> [128x256] -> GELU(exact) -> [256x128],
// residual. Lane owns 4 consecutive dims (d = lane*4+r) and 8 consecutive
// hidden units (j = lane*8+jr). Shuffle-broadcast register GEMMs.
// ---------------------------------------------------------------------------
__device__ __forceinline__ void ffn_warp(const float h[4], int lane,
                                         const float* __restrict__ ln_s,
                                         const float* __restrict__ ln_b,
                                         const float* __restrict__ W1,
                                         const float* __restrict__ b1,
                                         const float* __restrict__ W2,
                                         const float* __restrict__ b2,
                                         float out[4]) {
    // mean
    float s = h[0] + h[1] + h[2] + h[3];
    #pragma unroll
    for (int o = 16; o > 0; o >>= 1) s += __shfl_xor_sync(0xFFFFFFFFu, s, o);
    float mu = s * (1.0f / 128.0f);
    // variance
    float vs = 0.0f;
    #pragma unroll
    for (int r = 0; r < 4; r++) {
        float d = h[r] - mu;
        vs += d * d;
    }
    #pragma unroll
    for (int o = 16; o > 0; o >>= 1) vs += __shfl_xor_sync(0xFFFFFFFFu, vs, o);
    float rstd = rsqrtf(vs * (1.0f / 128.0f) + 1e-5f);

    float hn[4];
    #pragma unroll
    for (int r = 0; r < 4; r++) {
        int d = lane * 4 + r;
        hn[r] = (h[r] - mu) * rstd * ln_s[d] + ln_b[d];
    }

    // GEMM1: g[j] = sum_i hn[i] * W1[i][j] + b1[j]   (j = lane*8 + jr)
    float g[8];
    #pragma unroll
    for (int jr = 0; jr < 8; jr++) g[jr] = b1[lane * 8 + jr];

    #pragma unroll 8
    for (int i0 = 0; i0 < 32; i0++) {
        #pragma unroll
        for (int r = 0; r < 4; r++) {
            float hb = __shfl_sync(0xFFFFFFFFu, hn[r], i0);
            int i = i0 * 4 + r;
            float4 w1a = *(const float4*)&W1[(size_t)i * 256 + lane * 8];
            float4 w1b = *(const float4*)&W1[(size_t)i * 256 + lane * 8 + 4];
            g[0] = fmaf(hb, w1a.x, g[0]);
            g[1] = fmaf(hb, w1a.y, g[1]);
            g[2] = fmaf(hb, w1a.z, g[2]);
            g[3] = fmaf(hb, w1a.w, g[3]);
            g[4] = fmaf(hb, w1b.x, g[4]);
            g[5] = fmaf(hb, w1b.y, g[5]);
            g[6] = fmaf(hb, w1b.z, g[6]);
            g[7] = fmaf(hb, w1b.w, g[7]);
        }
    }

    // exact GELU: 0.5*x*(1+erf(x/sqrt(2)))
    #pragma unroll
    for (int jr = 0; jr < 8; jr++)
        g[jr] = 0.5f * g[jr] * (1.0f + erff(g[jr] * 0.70710678118654752f));

    // GEMM2: r[d] = sum_j g[j] * W2[j][d] + b2[d]   (d = lane*4 + r)
    float r4[4];
    #pragma unroll
    for (int r = 0; r < 4; r++) r4[r] = b2[lane * 4 + r];

    #pragma unroll 8
    for (int j0 = 0; j0 < 32; j0++) {
        #pragma unroll
        for (int jr = 0; jr < 8; jr++) {
            float gb = __shfl_sync(0xFFFFFFFFu, g[jr], j0);
            float4 w2 = *(const float4*)&W2[(size_t)(j0 * 8 + jr) * HID + lane * 4];
            r4[0] = fmaf(gb, w2.x, r4[0]);
            r4[1] = fmaf(gb, w2.y, r4[1]);
            r4[2] = fmaf(gb, w2.z, r4[2]);
            r4[3] = fmaf(gb, w2.w, r4[3]);
        }
    }

    #pragma unroll
    for (int r = 0; r < 4; r++) out[r] = h[r] + r4[r];
}

// ---------------------------------------------------------------------------
// K_ffn: one warp per (t, node); normalize accumulators, run both FFNs,
// write xs / cs / ss.
// ---------------------------------------------------------------------------
__global__ void ffn_kernel(const float* __restrict__ x,
                           const float* __restrict__ ln_s, const float* __restrict__ ln_b,
                           const float* __restrict__ W1, const float* __restrict__ b1,
                           const float* __restrict__ W2, const float* __restrict__ b2,
                           float* __restrict__ out) {
    int warp = (blockIdx.x * blockDim.x + threadIdx.x) >> 5;
    int lane = threadIdx.x & 31;
    if (warp >= T_WIN * N_NODES) return;

    size_t nodeoff = (size_t)warp * HID;     // warp == t*N_NODES + n
    int    segoff  = warp * NH + (lane >> 2);

    float4 ac = *(const float4*)&g_accc[nodeoff + lane * 4];
    float4 as = *(const float4*)&g_accs[nodeoff + lane * 4];
    float  sc = g_sc[segoff];
    float  ss = g_ss[segoff];
    float4 xv = *(const float4*)&x[nodeoff + lane * 4];

    float inv_c = 1.0f / (sc + 1e-16f);
    float inv_s = 1.0f / (ss + 1e-16f);

    float hc[4] = { ac.x * inv_c + xv.x, ac.y * inv_c + xv.y,
                    ac.z * inv_c + xv.z, ac.w * inv_c + xv.w };
    float hs[4] = { as.x * inv_s, as.y * inv_s, as.z * inv_s, as.w * inv_s };

    float oc[4], os[4];
    ffn_warp(hc, lane, ln_s, ln_b, W1, b1, W2, b2, oc);
    ffn_warp(hs, lane, ln_s, ln_b, W1, b1, W2, b2, os);

    const size_t S  = (size_t)T_WIN * N_NODES * HID;   // 19,200,000
    size_t ob = nodeoff + lane * 4;

    float4 vxs = make_float4(oc[0] + os[0], oc[1] + os[1], oc[2] + os[2], oc[3] + os[3]);
    float4 vcs = make_float4(oc[0], oc[1], oc[2], oc[3]);
    float4 vss = make_float4(os[0], os[1], os[2], os[3]);

    *(float4*)&out[ob]         = vxs;   // xs
    *(float4*)&out[S + ob]     = vcs;   // cs
    *(float4*)&out[2 * S + ob] = vss;   // ss
}

// ---------------------------------------------------------------------------
// Launch
// ---------------------------------------------------------------------------
extern "C" void kernel_launch(void* const* d_in, const int* in_sizes, int n_in,
                              void* d_out, int out_size) {
    const float* x    = (const float*)d_in[0];
    const int*   ei   = (const int*)  d_in[1];
    const float* Wq   = (const float*)d_in[2];
    const float* bq   = (const float*)d_in[3];
    const float* Wk   = (const float*)d_in[4];
    const float* bk   = (const float*)d_in[5];
    const float* Wv   = (const float*)d_in[6];
    const float* bv   = (const float*)d_in[7];
    const float* ln_s = (const float*)d_in[8];
    const float* ln_b = (const float*)d_in[9];
    const float* W1   = (const float*)d_in[10];
    const float* b1   = (const float*)d_in[11];
    const float* W2   = (const float*)d_in[12];
    const float* b2   = (const float*)d_in[13];
    float* out = (float*)d_out;

    clear_kernel<<<2048, 256>>>();

    qkv_kernel<<<dim3((M_ROWS + 63) / 64, 3), 256>>>(x, Wq, bq, Wk, bk, Wv, bv);

    dim3 egrid((E_PER_T + 31) / 32, N_PAIRS);
    edge_att_kernel<<<egrid, 256>>>(ei);
    edge_scatter_kernel<<<egrid, 256>>>(ei);

    ffn_kernel<<<(T_WIN * N_NODES + 7) / 8, 256>>>(x, ln_s, ln_b, W1, b1, W2, b2, out);
}

// round 2
// speedup vs baseline: 2.1099x; 2.1099x over previous
#include <cuda_runtime.h>
#include <math.h>

// ---------------------------------------------------------------------------
// Problem constants
// ---------------------------------------------------------------------------
#define N_NODES 50000
#define T_WIN   3
#define E_PER_T 100000
#define HID     128
#define NH      8
#define DK      16
#define M_ROWS  (T_WIN * N_NODES)          // 150000 rows
#define TN      (T_WIN * N_NODES)

// ---------------------------------------------------------------------------
// Device scratch
// ---------------------------------------------------------------------------
__device__ float  g_q[(size_t)M_ROWS * HID];
__device__ float  g_k[(size_t)M_ROWS * HID];
__device__ float  g_v[(size_t)M_ROWS * HID];
__device__ float2 g_s[(size_t)TN * NH];          // (sum_causal, sum_spurious)
__device__ float  g_accc[(size_t)TN * HID];
__device__ float  g_accs[(size_t)TN * HID];

// ---------------------------------------------------------------------------
// Packed fp32x2 helpers (B300 FFMA2 path)
// ---------------------------------------------------------------------------
typedef unsigned long long u64;

__device__ __forceinline__ u64 fma2(u64 a, u64 b, u64 c) {
    u64 d;
    asm("fma.rn.f32x2 %0, %1, %2, %3;" : "=l"(d) : "l"(a), "l"(b), "l"(c));
    return d;
}
__device__ __forceinline__ u64 pack2(float lo, float hi) {
    u64 r;
    asm("mov.b64 %0, {%1, %2};" : "=l"(r) : "f"(lo), "f"(hi));
    return r;
}
__device__ __forceinline__ float2 unpack2(u64 v) {
    float2 f;
    asm("mov.b64 {%0, %1}, %2;" : "=f"(f.x), "=f"(f.y) : "l"(v));
    return f;
}

// ---------------------------------------------------------------------------
// K_clear
// ---------------------------------------------------------------------------
__global__ void clear_kernel() {
    const size_t NB4 = (size_t)TN * HID / 4;     // 4.8M float4 per acc array
    const size_t NS  = (size_t)TN * NH;          // 1.2M float2
    size_t i      = (size_t)blockIdx.x * blockDim.x + threadIdx.x;
    size_t stride = (size_t)gridDim.x * blockDim.x;
    float4 z4 = make_float4(0.f, 0.f, 0.f, 0.f);
    for (size_t k = i; k < NB4; k += stride) {
        ((float4*)g_accc)[k] = z4;
        ((float4*)g_accs)[k] = z4;
    }
    float2 z2 = make_float2(0.f, 0.f);
    for (size_t k = i; k < NS; k += stride) g_s[k] = z2;
}

// ---------------------------------------------------------------------------
// K_qkv: [150000 x 128] @ [128 x 128] + b, packed f32x2 math
// BM=64, BN=128, BK=32, 256 threads, per-thread 4x8 (4x4 packed)
// ---------------------------------------------------------------------------
__global__ void __launch_bounds__(256) qkv_kernel(
        const float* __restrict__ x,
        const float* __restrict__ Wq, const float* __restrict__ bq,
        const float* __restrict__ Wk, const float* __restrict__ bk,
        const float* __restrict__ Wv, const float* __restrict__ bv) {
    const float* W; const float* b; float* out;
    if (blockIdx.y == 0)      { W = Wq; b = bq; out = g_q; }
    else if (blockIdx.y == 1) { W = Wk; b = bk; out = g_k; }
    else                      { W = Wv; b = bv; out = g_v; }

    __shared__ float Xs[64][33];
    __shared__ float Ws[32][128];

    const int tid  = threadIdx.x;
    const int m0   = blockIdx.x * 64;
    const int ty   = tid >> 4;
    const int tx   = tid & 15;
    const int row0 = ty * 4;
    const int col0 = tx * 8;

    u64 acc[4][4];
    #pragma unroll
    for (int i = 0; i < 4; i++)
        #pragma unroll
        for (int j = 0; j < 4; j++) acc[i][j] = 0ull;

    for (int kc = 0; kc < 128; kc += 32) {
        #pragma unroll
        for (int l = 0; l < 2; l++) {
            int f4 = tid + l * 256;
            int r  = f4 >> 3;
            int c4 = f4 & 7;
            int grow = m0 + r;
            float4 val = make_float4(0.f, 0.f, 0.f, 0.f);
            if (grow < M_ROWS)
                val = *(const float4*)&x[(size_t)grow * HID + kc + c4 * 4];
            Xs[r][c4 * 4 + 0] = val.x;
            Xs[r][c4 * 4 + 1] = val.y;
            Xs[r][c4 * 4 + 2] = val.z;
            Xs[r][c4 * 4 + 3] = val.w;
        }
        #pragma unroll
        for (int l = 0; l < 4; l++) {
            int f4 = tid + l * 256;
            int r  = f4 >> 5;
            int c4 = f4 & 31;
            *(float4*)&Ws[r][c4 * 4] =
                *(const float4*)&W[(size_t)(kc + r) * HID + c4 * 4];
        }
        __syncthreads();

        #pragma unroll
        for (int k = 0; k < 32; k++) {
            ulonglong2 wb0 = *(const ulonglong2*)&Ws[k][col0];
            ulonglong2 wb1 = *(const ulonglong2*)&Ws[k][col0 + 4];
            #pragma unroll
            for (int i = 0; i < 4; i++) {
                u64 ap = pack2(Xs[row0 + i][k], Xs[row0 + i][k]);
                acc[i][0] = fma2(ap, wb0.x, acc[i][0]);
                acc[i][1] = fma2(ap, wb0.y, acc[i][1]);
                acc[i][2] = fma2(ap, wb1.x, acc[i][2]);
                acc[i][3] = fma2(ap, wb1.y, acc[i][3]);
            }
        }
        __syncthreads();
    }

    #pragma unroll
    for (int i = 0; i < 4; i++) {
        int grow = m0 + row0 + i;
        if (grow < M_ROWS) {
            float o[8];
            #pragma unroll
            for (int j = 0; j < 4; j++) {
                float2 v = unpack2(acc[i][j]);
                o[j * 2]     = v.x + b[col0 + j * 2];
                o[j * 2 + 1] = v.y + b[col0 + j * 2 + 1];
            }
            *(float4*)&out[(size_t)grow * HID + col0]     = make_float4(o[0], o[1], o[2], o[3]);
            *(float4*)&out[(size_t)grow * HID + col0 + 4] = make_float4(o[4], o[5], o[6], o[7]);
        }
    }
}

// ---------------------------------------------------------------------------
// K_edge: fused attention + scatter. One thread = (t_src, edge, head).
// k/v gathered ONCE per (t_src, edge); looped over t_tar >= t_src.
// No max-shift (exp(a)/sum == exp(a-M)/sum analytically; logits are O(3)).
// Vector atomics (float4/float2) cut L2 RED ops 3.8x.
// ---------------------------------------------------------------------------
__global__ void __launch_bounds__(256) edge_kernel(const int* __restrict__ ei) {
    const int t_src = blockIdx.y;
    int e = blockIdx.x * 32 + (threadIdx.x >> 3);
    int h = threadIdx.x & 7;
    if (e >= E_PER_T) return;

    int src = ei[(size_t)t_src * 2 * E_PER_T + e];
    int tar = ei[(size_t)t_src * 2 * E_PER_T + E_PER_T + e];

    const float4* kp = (const float4*)(g_k + ((size_t)t_src * N_NODES + src) * HID + h * DK);
    const float4* vp = (const float4*)(g_v + ((size_t)t_src * N_NODES + src) * HID + h * DK);
    float4 kv[4], vv[4];
    #pragma unroll
    for (int i = 0; i < 4; i++) { kv[i] = kp[i]; vv[i] = vp[i]; }

    for (int t_tar = t_src; t_tar < T_WIN; t_tar++) {
        size_t node = (size_t)t_tar * N_NODES + tar;
        const float4* qp = (const float4*)(g_q + node * HID + h * DK);
        float a = 0.0f;
        #pragma unroll
        for (int i = 0; i < 4; i++) {
            float4 qv = qp[i];
            a = fmaf(qv.x, kv[i].x, a);
            a = fmaf(qv.y, kv[i].y, a);
            a = fmaf(qv.z, kv[i].z, a);
            a = fmaf(qv.w, kv[i].w, a);
        }
        a *= 0.25f;                       // 1/sqrt(16)

        float ec = expf(a);
        float es = expf(-a);

        atomicAdd(&g_s[node * NH + h], make_float2(ec, es));

        float* pc = g_accc + node * HID + h * DK;
        float* ps = g_accs + node * HID + h * DK;
        #pragma unroll
        for (int q4 = 0; q4 < 4; q4++) {
            float4 v = vv[q4];
            atomicAdd((float4*)(pc + q4 * 4),
                      make_float4(ec * v.x, ec * v.y, ec * v.z, ec * v.w));
            atomicAdd((float4*)(ps + q4 * 4),
                      make_float4(es * v.x, es * v.y, es * v.z, es * v.w));
        }
    }
}

// ---------------------------------------------------------------------------
// K_ffn: one warp handles 2 nodes (4 FFN instances: c0,s0,c1,s1).
// Packed f32x2 accumulators; broadcast operands staged in smem as
// pre-duplicated (h,h) u64 pairs. W1/W2 loads amortize over 4 instances.
// ---------------------------------------------------------------------------
__device__ __forceinline__ float gelu_exact(float v) {
    return 0.5f * v * (1.0f + erff(v * 0.70710678118654752f));
}

__device__ __forceinline__ void ln_store(const float h[4], int lane,
                                         float4 lns, float4 lnb,
                                         u64* __restrict__ dst) {
    float s1 = h[0] + h[1] + h[2] + h[3];
    float s2 = h[0]*h[0] + h[1]*h[1] + h[2]*h[2] + h[3]*h[3];
    #pragma unroll
    for (int o = 16; o > 0; o >>= 1) {
        s1 += __shfl_xor_sync(0xFFFFFFFFu, s1, o);
        s2 += __shfl_xor_sync(0xFFFFFFFFu, s2, o);
    }
    float mu   = s1 * (1.0f / 128.0f);
    float var  = s2 * (1.0f / 128.0f) - mu * mu;
    float rstd = rsqrtf(var + 1e-5f);

    float hn0 = (h[0] - mu) * rstd * lns.x + lnb.x;
    float hn1 = (h[1] - mu) * rstd * lns.y + lnb.y;
    float hn2 = (h[2] - mu) * rstd * lns.z + lnb.z;
    float hn3 = (h[3] - mu) * rstd * lns.w + lnb.w;
    dst[lane * 4 + 0] = pack2(hn0, hn0);
    dst[lane * 4 + 1] = pack2(hn1, hn1);
    dst[lane * 4 + 2] = pack2(hn2, hn2);
    dst[lane * 4 + 3] = pack2(hn3, hn3);
}

__global__ void __launch_bounds__(256) ffn_kernel(
        const float* __restrict__ x,
        const float* __restrict__ ln_s, const float* __restrict__ ln_b,
        const float* __restrict__ W1, const float* __restrict__ b1,
        const float* __restrict__ W2, const float* __restrict__ b2,
        float* __restrict__ out) {
    // per-warp 4KB scratch: phase1 = u64 hn[4][128] (dup pairs),
    //                       phase2 = float g[4][256]
    __shared__ u64 sbuf[8][512];

    const int wib  = threadIdx.x >> 5;
    const int lane = threadIdx.x & 31;
    const int wg   = blockIdx.x * 8 + wib;     // 0 .. 74999 (exact)

    u64   (*hnbuf)[128] = (u64 (*)[128])sbuf[wib];
    float (*gbuf)[256]  = (float (*)[256])sbuf[wib];

    const float4 lns = *(const float4*)&ln_s[lane * 4];
    const float4 lnb = *(const float4*)&ln_b[lane * 4];

    float hsave[4][4];

    #pragma unroll
    for (int nn = 0; nn < 2; nn++) {
        size_t node = (size_t)wg * 2 + nn;
        size_t off  = node * HID + lane * 4;
        float4 ac = *(const float4*)&g_accc[off];
        float4 as = *(const float4*)&g_accs[off];
        float4 xv = *(const float4*)&x[off];
        float2 sm = g_s[node * NH + (lane >> 2)];
        float ic = 1.0f / (sm.x + 1e-16f);
        float is = 1.0f / (sm.y + 1e-16f);

        float hc[4] = { fmaf(ac.x, ic, xv.x), fmaf(ac.y, ic, xv.y),
                        fmaf(ac.z, ic, xv.z), fmaf(ac.w, ic, xv.w) };
        float hs[4] = { as.x * is, as.y * is, as.z * is, as.w * is };

        #pragma unroll
        for (int r = 0; r < 4; r++) { hsave[nn*2][r] = hc[r]; hsave[nn*2+1][r] = hs[r]; }

        ln_store(hc, lane, lns, lnb, hnbuf[nn * 2 + 0]);
        ln_store(hs, lane, lns, lnb, hnbuf[nn * 2 + 1]);
    }
    __syncwarp();

    // ---- GEMM1: g[f][j] = sum_i hn[f][i] * W1[i][j] + b1[j], j = lane*8..+8
    u64 a1[4][4];
    {
        ulonglong2 bA = *(const ulonglong2*)&b1[lane * 8];
        ulonglong2 bB = *(const ulonglong2*)&b1[lane * 8 + 4];
        #pragma unroll
        for (int f = 0; f < 4; f++) {
            a1[f][0] = bA.x; a1[f][1] = bA.y; a1[f][2] = bB.x; a1[f][3] = bB.y;
        }
    }
    #pragma unroll 4
    for (int i0 = 0; i0 < 64; i0++) {
        const int i = 2 * i0;
        ulonglong2 hp[4];
        #pragma unroll
        for (int f = 0; f < 4; f++) hp[f] = *(const ulonglong2*)&hnbuf[f][i];

        const float* w0 = W1 + (size_t)i * 256 + lane * 8;
        const float* w1 = w0 + 256;
        ulonglong2 wA0 = *(const ulonglong2*)w0;
        ulonglong2 wB0 = *(const ulonglong2*)(w0 + 4);
        ulonglong2 wA1 = *(const ulonglong2*)w1;
        ulonglong2 wB1 = *(const ulonglong2*)(w1 + 4);

        #pragma unroll
        for (int f = 0; f < 4; f++) {
            a1[f][0] = fma2(hp[f].x, wA0.x, a1[f][0]);
            a1[f][1] = fma2(hp[f].x, wA0.y, a1[f][1]);
            a1[f][2] = fma2(hp[f].x, wB0.x, a1[f][2]);
            a1[f][3] = fma2(hp[f].x, wB0.y, a1[f][3]);
            a1[f][0] = fma2(hp[f].y, wA1.x, a1[f][0]);
            a1[f][1] = fma2(hp[f].y, wA1.y, a1[f][1]);
            a1[f][2] = fma2(hp[f].y, wB1.x, a1[f][2]);
            a1[f][3] = fma2(hp[f].y, wB1.y, a1[f][3]);
        }
    }
    __syncwarp();   // done reading hnbuf; gbuf aliases it

    // ---- GELU, stage g to smem
    #pragma unroll
    for (int f = 0; f < 4; f++) {
        float2* gd = (float2*)&gbuf[f][lane * 8];
        #pragma unroll
        for (int p = 0; p < 4; p++) {
            float2 v = unpack2(a1[f][p]);
            gd[p] = make_float2(gelu_exact(v.x), gelu_exact(v.y));
        }
    }
    __syncwarp();

    // ---- GEMM2: r[f][d] = sum_j g[f][j] * W2[j][d] + b2[d], d = lane*4..+4
    u64 a2[4][2];
    {
        ulonglong2 bb = *(const ulonglong2*)&b2[lane * 4];
        #pragma unroll
        for (int f = 0; f < 4; f++) { a2[f][0] = bb.x; a2[f][1] = bb.y; }
    }
    #pragma unroll 4
    for (int j0 = 0; j0 < 128; j0++) {
        const int j = 2 * j0;
        float2 gj[4];
        #pragma unroll
        for (int f = 0; f < 4; f++) gj[f] = *(const float2*)&gbuf[f][j];

        ulonglong2 w0 = *(const ulonglong2*)(W2 + (size_t)j * 128 + lane * 4);
        ulonglong2 w1 = *(const ulonglong2*)(W2 + (size_t)(j + 1) * 128 + lane * 4);

        #pragma unroll
        for (int f = 0; f < 4; f++) {
            u64 p0 = pack2(gj[f].x, gj[f].x);
            u64 p1 = pack2(gj[f].y, gj[f].y);
            a2[f][0] = fma2(p0, w0.x, a2[f][0]);
            a2[f][1] = fma2(p0, w0.y, a2[f][1]);
            a2[f][0] = fma2(p1, w1.x, a2[f][0]);
            a2[f][1] = fma2(p1, w1.y, a2[f][1]);
        }
    }

    // ---- residual + output (xs = c+s, cs = c, ss = s)
    const size_t S = (size_t)TN * HID;
    #pragma unroll
    for (int nn = 0; nn < 2; nn++) {
        size_t ob = ((size_t)wg * 2 + nn) * HID + lane * 4;
        float2 c01 = unpack2(a2[nn*2][0]);
        float2 c23 = unpack2(a2[nn*2][1]);
        float2 s01 = unpack2(a2[nn*2+1][0]);
        float2 s23 = unpack2(a2[nn*2+1][1]);
        float oc[4] = { hsave[nn*2][0] + c01.x, hsave[nn*2][1] + c01.y,
                        hsave[nn*2][2] + c23.x, hsave[nn*2][3] + c23.y };
        float os[4] = { hsave[nn*2+1][0] + s01.x, hsave[nn*2+1][1] + s01.y,
                        hsave[nn*2+1][2] + s23.x, hsave[nn*2+1][3] + s23.y };

        *(float4*)&out[ob]         = make_float4(oc[0]+os[0], oc[1]+os[1],
                                                 oc[2]+os[2], oc[3]+os[3]);
        *(float4*)&out[S + ob]     = make_float4(oc[0], oc[1], oc[2], oc[3]);
        *(float4*)&out[2*S + ob]   = make_float4(os[0], os[1], os[2], os[3]);
    }
}

// ---------------------------------------------------------------------------
// Launch
// ---------------------------------------------------------------------------
extern "C" void kernel_launch(void* const* d_in, const int* in_sizes, int n_in,
                              void* d_out, int out_size) {
    const float* x    = (const float*)d_in[0];
    const int*   ei   = (const int*)  d_in[1];
    const float* Wq   = (const float*)d_in[2];
    const float* bq   = (const float*)d_in[3];
    const float* Wk   = (const float*)d_in[4];
    const float* bk   = (const float*)d_in[5];
    const float* Wv   = (const float*)d_in[6];
    const float* bv   = (const float*)d_in[7];
    const float* ln_s = (const float*)d_in[8];
    const float* ln_b = (const float*)d_in[9];
    const float* W1   = (const float*)d_in[10];
    const float* b1   = (const float*)d_in[11];
    const float* W2   = (const float*)d_in[12];
    const float* b2   = (const float*)d_in[13];
    float* out = (float*)d_out;

    clear_kernel<<<1024, 256>>>();

    qkv_kernel<<<dim3((M_ROWS + 63) / 64, 3), 256>>>(x, Wq, bq, Wk, bk, Wv, bv);

    edge_kernel<<<dim3((E_PER_T + 31) / 32, T_WIN), 256>>>(ei);

    ffn_kernel<<<(TN / 2) / 8, 256>>>(x, ln_s, ln_b, W1, b1, W2, b2, out);
}

// round 3
// speedup vs baseline: 2.1827x; 1.0345x over previous
#include <cuda_runtime.h>
#include <math.h>

// ---------------------------------------------------------------------------
// Problem constants
// ---------------------------------------------------------------------------
#define N_NODES 50000
#define T_WIN   3
#define E_PER_T 100000
#define HID     128
#define NH      8
#define DK      16
#define M_ROWS  (T_WIN * N_NODES)          // 150000 rows
#define TN      (T_WIN * N_NODES)

// ---------------------------------------------------------------------------
// Device scratch
// ---------------------------------------------------------------------------
__device__ float  g_q[(size_t)M_ROWS * HID];
__device__ float  g_k[(size_t)M_ROWS * HID];
__device__ float  g_v[(size_t)M_ROWS * HID];
__device__ float2 g_s[(size_t)TN * NH];          // (sum_causal, sum_spurious)
__device__ float  g_accc[(size_t)TN * HID];
__device__ float  g_accs[(size_t)TN * HID];

// ---------------------------------------------------------------------------
// Packed fp32x2 helpers (B300 FFMA2 path)
// ---------------------------------------------------------------------------
typedef unsigned long long u64;

__device__ __forceinline__ u64 fma2(u64 a, u64 b, u64 c) {
    u64 d;
    asm("fma.rn.f32x2 %0, %1, %2, %3;" : "=l"(d) : "l"(a), "l"(b), "l"(c));
    return d;
}
__device__ __forceinline__ u64 pack2(float lo, float hi) {
    u64 r;
    asm("mov.b64 %0, {%1, %2};" : "=l"(r) : "f"(lo), "f"(hi));
    return r;
}
__device__ __forceinline__ float2 unpack2(u64 v) {
    float2 f;
    asm("mov.b64 {%0, %1}, %2;" : "=f"(f.x), "=f"(f.y) : "l"(v));
    return f;
}

// ---------------------------------------------------------------------------
// K_clear
// ---------------------------------------------------------------------------
__global__ void clear_kernel() {
    const size_t NB4 = (size_t)TN * HID / 4;     // 4.8M float4 per acc array
    const size_t NS  = (size_t)TN * NH;          // 1.2M float2
    size_t i      = (size_t)blockIdx.x * blockDim.x + threadIdx.x;
    size_t stride = (size_t)gridDim.x * blockDim.x;
    float4 z4 = make_float4(0.f, 0.f, 0.f, 0.f);
    for (size_t k = i; k < NB4; k += stride) {
        ((float4*)g_accc)[k] = z4;
        ((float4*)g_accs)[k] = z4;
    }
    float2 z2 = make_float2(0.f, 0.f);
    for (size_t k = i; k < NS; k += stride) g_s[k] = z2;
}

// ---------------------------------------------------------------------------
// K_qkv: [150000 x 128] @ [128 x 128] + b, packed f32x2 math
// BM=64, BN=128, BK=32, 256 threads, per-thread tile 4x8 (4x4 packed)
// ---------------------------------------------------------------------------
__global__ void __launch_bounds__(256) qkv_kernel(
        const float* __restrict__ x,
        const float* __restrict__ Wq, const float* __restrict__ bq,
        const float* __restrict__ Wk, const float* __restrict__ bk,
        const float* __restrict__ Wv, const float* __restrict__ bv) {
    const float* W; const float* b; float* out;
    if (blockIdx.y == 0)      { W = Wq; b = bq; out = g_q; }
    else if (blockIdx.y == 1) { W = Wk; b = bk; out = g_k; }
    else                      { W = Wv; b = bv; out = g_v; }

    __shared__ float Xs[64][33];
    __shared__ float Ws[32][128];

    const int tid  = threadIdx.x;
    const int m0   = blockIdx.x * 64;
    const int ty   = tid >> 4;
    const int tx   = tid & 15;
    const int row0 = ty * 4;
    const int col0 = tx * 8;

    u64 acc[4][4];
    #pragma unroll
    for (int i = 0; i < 4; i++)
        #pragma unroll
        for (int j = 0; j < 4; j++) acc[i][j] = 0ull;

    for (int kc = 0; kc < 128; kc += 32) {
        #pragma unroll
        for (int l = 0; l < 2; l++) {
            int f4 = tid + l * 256;
            int r  = f4 >> 3;
            int c4 = f4 & 7;
            int grow = m0 + r;
            float4 val = make_float4(0.f, 0.f, 0.f, 0.f);
            if (grow < M_ROWS)
                val = *(const float4*)&x[(size_t)grow * HID + kc + c4 * 4];
            Xs[r][c4 * 4 + 0] = val.x;
            Xs[r][c4 * 4 + 1] = val.y;
            Xs[r][c4 * 4 + 2] = val.z;
            Xs[r][c4 * 4 + 3] = val.w;
        }
        #pragma unroll
        for (int l = 0; l < 4; l++) {
            int f4 = tid + l * 256;
            int r  = f4 >> 5;
            int c4 = f4 & 31;
            *(float4*)&Ws[r][c4 * 4] =
                *(const float4*)&W[(size_t)(kc + r) * HID + c4 * 4];
        }
        __syncthreads();

        #pragma unroll
        for (int k = 0; k < 32; k++) {
            ulonglong2 wb0 = *(const ulonglong2*)&Ws[k][col0];
            ulonglong2 wb1 = *(const ulonglong2*)&Ws[k][col0 + 4];
            #pragma unroll
            for (int i = 0; i < 4; i++) {
                u64 ap = pack2(Xs[row0 + i][k], Xs[row0 + i][k]);
                acc[i][0] = fma2(ap, wb0.x, acc[i][0]);
                acc[i][1] = fma2(ap, wb0.y, acc[i][1]);
                acc[i][2] = fma2(ap, wb1.x, acc[i][2]);
                acc[i][3] = fma2(ap, wb1.y, acc[i][3]);
            }
        }
        __syncthreads();
    }

    #pragma unroll
    for (int i = 0; i < 4; i++) {
        int grow = m0 + row0 + i;
        if (grow < M_ROWS) {
            float o[8];
            #pragma unroll
            for (int j = 0; j < 4; j++) {
                float2 v = unpack2(acc[i][j]);
                o[j * 2]     = v.x + b[col0 + j * 2];
                o[j * 2 + 1] = v.y + b[col0 + j * 2 + 1];
            }
            *(float4*)&out[(size_t)grow * HID + col0]     = make_float4(o[0], o[1], o[2], o[3]);
            *(float4*)&out[(size_t)grow * HID + col0 + 4] = make_float4(o[4], o[5], o[6], o[7]);
        }
    }
}

// ---------------------------------------------------------------------------
// K_edge: fused attention + scatter. One thread = (t_src, edge, head).
// k/v gathered ONCE per (t_src, edge); looped over t_tar >= t_src.
// No max-shift (exp(a)/sum == exp(a-M)/sum analytically; logits are O(3)).
// Vector atomics (float4/float2).
// ---------------------------------------------------------------------------
__global__ void __launch_bounds__(256) edge_kernel(const int* __restrict__ ei) {
    const int t_src = blockIdx.y;
    int e = blockIdx.x * 32 + (threadIdx.x >> 3);
    int h = threadIdx.x & 7;
    if (e >= E_PER_T) return;

    int src = ei[(size_t)t_src * 2 * E_PER_T + e];
    int tar = ei[(size_t)t_src * 2 * E_PER_T + E_PER_T + e];

    const float4* kp = (const float4*)(g_k + ((size_t)t_src * N_NODES + src) * HID + h * DK);
    const float4* vp = (const float4*)(g_v + ((size_t)t_src * N_NODES + src) * HID + h * DK);
    float4 kv[4], vv[4];
    #pragma unroll
    for (int i = 0; i < 4; i++) { kv[i] = kp[i]; vv[i] = vp[i]; }

    for (int t_tar = t_src; t_tar < T_WIN; t_tar++) {
        size_t node = (size_t)t_tar * N_NODES + tar;
        const float4* qp = (const float4*)(g_q + node * HID + h * DK);
        float a = 0.0f;
        #pragma unroll
        for (int i = 0; i < 4; i++) {
            float4 qv = qp[i];
            a = fmaf(qv.x, kv[i].x, a);
            a = fmaf(qv.y, kv[i].y, a);
            a = fmaf(qv.z, kv[i].z, a);
            a = fmaf(qv.w, kv[i].w, a);
        }
        a *= 0.25f;                       // 1/sqrt(16)

        float ec = expf(a);
        float es = expf(-a);

        atomicAdd(&g_s[node * NH + h], make_float2(ec, es));

        float* pc = g_accc + node * HID + h * DK;
        float* ps = g_accs + node * HID + h * DK;
        #pragma unroll
        for (int q4 = 0; q4 < 4; q4++) {
            float4 v = vv[q4];
            atomicAdd((float4*)(pc + q4 * 4),
                      make_float4(ec * v.x, ec * v.y, ec * v.z, ec * v.w));
            atomicAdd((float4*)(ps + q4 * 4),
                      make_float4(es * v.x, es * v.y, es * v.z, es * v.w));
        }
    }
}

// ---------------------------------------------------------------------------
// K_ffn v3: one warp handles 4 nodes (8 FFN instances).
// - W L1 bytes per fma2 halved vs F=4.
// - hn stored in smem as plain floats (LDS.64); (h,h) pairs built with
//   register mov.b64 (ALU pipe) instead of duplicated LDS.128.
// - h recomputed in epilogue from L1-hot loads (no hsave register cost).
// ---------------------------------------------------------------------------
__device__ __forceinline__ float gelu_exact(float v) {
    return 0.5f * v * (1.0f + erff(v * 0.70710678118654752f));
}

__device__ __forceinline__ void compute_h(const float* __restrict__ x,
                                          size_t node, int lane,
                                          float hc[4], float hs[4]) {
    size_t off  = node * HID + lane * 4;
    float4 ac = *(const float4*)&g_accc[off];
    float4 as = *(const float4*)&g_accs[off];
    float4 xv = *(const float4*)&x[off];
    float2 sm = g_s[node * NH + (lane >> 2)];
    float ic = 1.0f / (sm.x + 1e-16f);
    float is = 1.0f / (sm.y + 1e-16f);
    hc[0] = fmaf(ac.x, ic, xv.x); hc[1] = fmaf(ac.y, ic, xv.y);
    hc[2] = fmaf(ac.z, ic, xv.z); hc[3] = fmaf(ac.w, ic, xv.w);
    hs[0] = as.x * is; hs[1] = as.y * is; hs[2] = as.z * is; hs[3] = as.w * is;
}

__device__ __forceinline__ void ln_store(const float h[4], int lane,
                                         float4 lns, float4 lnb,
                                         float* __restrict__ dst) {
    float s1 = h[0] + h[1] + h[2] + h[3];
    float s2 = h[0]*h[0] + h[1]*h[1] + h[2]*h[2] + h[3]*h[3];
    #pragma unroll
    for (int o = 16; o > 0; o >>= 1) {
        s1 += __shfl_xor_sync(0xFFFFFFFFu, s1, o);
        s2 += __shfl_xor_sync(0xFFFFFFFFu, s2, o);
    }
    float mu   = s1 * (1.0f / 128.0f);
    float var  = s2 * (1.0f / 128.0f) - mu * mu;
    float rstd = rsqrtf(var + 1e-5f);

    float hn0 = (h[0] - mu) * rstd * lns.x + lnb.x;
    float hn1 = (h[1] - mu) * rstd * lns.y + lnb.y;
    float hn2 = (h[2] - mu) * rstd * lns.z + lnb.z;
    float hn3 = (h[3] - mu) * rstd * lns.w + lnb.w;
    *(float4*)&dst[lane * 4] = make_float4(hn0, hn1, hn2, hn3);
}

__global__ void __launch_bounds__(256) ffn_kernel(
        const float* __restrict__ x,
        const float* __restrict__ ln_s, const float* __restrict__ ln_b,
        const float* __restrict__ W1, const float* __restrict__ b1,
        const float* __restrict__ W2, const float* __restrict__ b2,
        float* __restrict__ out) {
    // per-warp 8KB scratch:
    //   phase1: hn[8][128] floats (first 4KB)
    //   phase2: g[8][256] floats (8KB, aliased; syncwarp separates)
    __shared__ float sbuf[8][2048];

    const int wib  = threadIdx.x >> 5;
    const int lane = threadIdx.x & 31;
    const int wg   = blockIdx.x * 8 + wib;     // warp id over TN/4 = 37500
    if (wg >= TN / 4) return;

    float* hnf = sbuf[wib];
    float* gb  = sbuf[wib];

    const float4 lns = *(const float4*)&ln_s[lane * 4];
    const float4 lnb = *(const float4*)&ln_b[lane * 4];

    // ---- phase 0: h + LayerNorm for 8 instances (f = nn*2 + {c,s})
    #pragma unroll
    for (int nn = 0; nn < 4; nn++) {
        size_t node = (size_t)wg * 4 + nn;
        float hc[4], hs[4];
        compute_h(x, node, lane, hc, hs);
        ln_store(hc, lane, lns, lnb, &hnf[(nn * 2 + 0) * 128]);
        ln_store(hs, lane, lns, lnb, &hnf[(nn * 2 + 1) * 128]);
    }
    __syncwarp();

    // ---- GEMM1: g[f][j] = sum_i hn[f][i] * W1[i][j] + b1[j], j = lane*8..+8
    u64 a1[8][4];
    {
        ulonglong2 bA = *(const ulonglong2*)&b1[lane * 8];
        ulonglong2 bB = *(const ulonglong2*)&b1[lane * 8 + 4];
        #pragma unroll
        for (int f = 0; f < 8; f++) {
            a1[f][0] = bA.x; a1[f][1] = bA.y; a1[f][2] = bB.x; a1[f][3] = bB.y;
        }
    }
    #pragma unroll 2
    for (int i = 0; i < 128; i += 2) {
        const float* w = W1 + (size_t)i * 256 + lane * 8;
        ulonglong2 wA0 = *(const ulonglong2*)w;
        ulonglong2 wB0 = *(const ulonglong2*)(w + 4);
        ulonglong2 wA1 = *(const ulonglong2*)(w + 256);
        ulonglong2 wB1 = *(const ulonglong2*)(w + 260);

        #pragma unroll
        for (int f = 0; f < 8; f++) {
            float2 hv = *(const float2*)&hnf[f * 128 + i];
            u64 p0 = pack2(hv.x, hv.x);
            u64 p1 = pack2(hv.y, hv.y);
            a1[f][0] = fma2(p0, wA0.x, a1[f][0]);
            a1[f][1] = fma2(p0, wA0.y, a1[f][1]);
            a1[f][2] = fma2(p0, wB0.x, a1[f][2]);
            a1[f][3] = fma2(p0, wB0.y, a1[f][3]);
            a1[f][0] = fma2(p1, wA1.x, a1[f][0]);
            a1[f][1] = fma2(p1, wA1.y, a1[f][1]);
            a1[f][2] = fma2(p1, wB1.x, a1[f][2]);
            a1[f][3] = fma2(p1, wB1.y, a1[f][3]);
        }
    }
    __syncwarp();   // done reading hnf; gb aliases it

    // ---- GELU, stage g to smem
    #pragma unroll
    for (int f = 0; f < 8; f++) {
        float2 v0 = unpack2(a1[f][0]);
        float2 v1 = unpack2(a1[f][1]);
        float2 v2 = unpack2(a1[f][2]);
        float2 v3 = unpack2(a1[f][3]);
        float* gd = &gb[f * 256 + lane * 8];
        *(float4*)gd       = make_float4(gelu_exact(v0.x), gelu_exact(v0.y),
                                         gelu_exact(v1.x), gelu_exact(v1.y));
        *(float4*)(gd + 4) = make_float4(gelu_exact(v2.x), gelu_exact(v2.y),
                                         gelu_exact(v3.x), gelu_exact(v3.y));
    }
    __syncwarp();

    // ---- GEMM2: r[f][d] = sum_j g[f][j] * W2[j][d] + b2[d], d = lane*4..+4
    u64 a2[8][2];
    {
        ulonglong2 bb = *(const ulonglong2*)&b2[lane * 4];
        #pragma unroll
        for (int f = 0; f < 8; f++) { a2[f][0] = bb.x; a2[f][1] = bb.y; }
    }
    #pragma unroll 2
    for (int j = 0; j < 256; j += 2) {
        const float* w = W2 + (size_t)j * 128 + lane * 4;
        ulonglong2 w0 = *(const ulonglong2*)w;
        ulonglong2 w1 = *(const ulonglong2*)(w + 128);

        #pragma unroll
        for (int f = 0; f < 8; f++) {
            float2 gj = *(const float2*)&gb[f * 256 + j];
            u64 p0 = pack2(gj.x, gj.x);
            u64 p1 = pack2(gj.y, gj.y);
            a2[f][0] = fma2(p0, w0.x, a2[f][0]);
            a2[f][1] = fma2(p0, w0.y, a2[f][1]);
            a2[f][0] = fma2(p1, w1.x, a2[f][0]);
            a2[f][1] = fma2(p1, w1.y, a2[f][1]);
        }
    }

    // ---- epilogue: recompute h (L1-hot), residual, write xs/cs/ss
    const size_t S = (size_t)TN * HID;
    #pragma unroll
    for (int nn = 0; nn < 4; nn++) {
        size_t node = (size_t)wg * 4 + nn;
        float hc[4], hs[4];
        compute_h(x, node, lane, hc, hs);

        float2 c01 = unpack2(a2[nn * 2][0]);
        float2 c23 = unpack2(a2[nn * 2][1]);
        float2 s01 = unpack2(a2[nn * 2 + 1][0]);
        float2 s23 = unpack2(a2[nn * 2 + 1][1]);
        float oc[4] = { hc[0] + c01.x, hc[1] + c01.y, hc[2] + c23.x, hc[3] + c23.y };
        float os[4] = { hs[0] + s01.x, hs[1] + s01.y, hs[2] + s23.x, hs[3] + s23.y };

        size_t ob = node * HID + lane * 4;
        *(float4*)&out[ob]       = make_float4(oc[0]+os[0], oc[1]+os[1],
                                               oc[2]+os[2], oc[3]+os[3]);
        *(float4*)&out[S + ob]   = make_float4(oc[0], oc[1], oc[2], oc[3]);
        *(float4*)&out[2*S + ob] = make_float4(os[0], os[1], os[2], os[3]);
    }
}

// ---------------------------------------------------------------------------
// Launch
// ---------------------------------------------------------------------------
extern "C" void kernel_launch(void* const* d_in, const int* in_sizes, int n_in,
                              void* d_out, int out_size) {
    const float* x    = (const float*)d_in[0];
    const int*   ei   = (const int*)  d_in[1];
    const float* Wq   = (const float*)d_in[2];
    const float* bq   = (const float*)d_in[3];
    const float* Wk   = (const float*)d_in[4];
    const float* bk   = (const float*)d_in[5];
    const float* Wv   = (const float*)d_in[6];
    const float* bv   = (const float*)d_in[7];
    const float* ln_s = (const float*)d_in[8];
    const float* ln_b = (const float*)d_in[9];
    const float* W1   = (const float*)d_in[10];
    const float* b1   = (const float*)d_in[11];
    const float* W2   = (const float*)d_in[12];
    const float* b2   = (const float*)d_in[13];
    float* out = (float*)d_out;

    clear_kernel<<<1024, 256>>>();

    qkv_kernel<<<dim3((M_ROWS + 63) / 64, 3), 256>>>(x, Wq, bq, Wk, bk, Wv, bv);

    edge_kernel<<<dim3((E_PER_T + 31) / 32, T_WIN), 256>>>(ei);

    // 37500 warps total (4 nodes each), 8 warps per block
    ffn_kernel<<<(TN / 4 + 7) / 8, 256>>>(x, ln_s, ln_b, W1, b1, W2, b2, out);
}

// round 4
// speedup vs baseline: 2.7189x; 1.2457x over previous
#include <cuda_runtime.h>
#include <math.h>

// ---------------------------------------------------------------------------
// Problem constants
// ---------------------------------------------------------------------------
#define N_NODES 50000
#define T_WIN   3
#define E_PER_T 100000
#define HID     128
#define NH      8
#define DK      16
#define M_ROWS  (T_WIN * N_NODES)          // 150000 rows
#define TN      (T_WIN * N_NODES)

// ---------------------------------------------------------------------------
// Device scratch
// ---------------------------------------------------------------------------
__device__ float  g_q[(size_t)M_ROWS * HID];
__device__ float  g_k[(size_t)M_ROWS * HID];
__device__ float  g_v[(size_t)M_ROWS * HID];
__device__ float2 g_s[(size_t)TN * NH];          // (sum_causal, sum_spurious)
__device__ float  g_accc[(size_t)TN * HID];
__device__ float  g_accs[(size_t)TN * HID];

// ---------------------------------------------------------------------------
// Packed fp32x2 helpers (B300 FFMA2 path)
// ---------------------------------------------------------------------------
typedef unsigned long long u64;

__device__ __forceinline__ u64 fma2(u64 a, u64 b, u64 c) {
    u64 d;
    asm("fma.rn.f32x2 %0, %1, %2, %3;" : "=l"(d) : "l"(a), "l"(b), "l"(c));
    return d;
}
__device__ __forceinline__ u64 pack2(float lo, float hi) {
    u64 r;
    asm("mov.b64 %0, {%1, %2};" : "=l"(r) : "f"(lo), "f"(hi));
    return r;
}
__device__ __forceinline__ float2 unpack2(u64 v) {
    float2 f;
    asm("mov.b64 {%0, %1}, %2;" : "=f"(f.x), "=f"(f.y) : "l"(v));
    return f;
}

// ---------------------------------------------------------------------------
// K_clear
// ---------------------------------------------------------------------------
__global__ void clear_kernel() {
    const size_t NB4 = (size_t)TN * HID / 4;     // 4.8M float4 per acc array
    const size_t NS  = (size_t)TN * NH;          // 1.2M float2
    size_t i      = (size_t)blockIdx.x * blockDim.x + threadIdx.x;
    size_t stride = (size_t)gridDim.x * blockDim.x;
    float4 z4 = make_float4(0.f, 0.f, 0.f, 0.f);
    for (size_t k = i; k < NB4; k += stride) {
        ((float4*)g_accc)[k] = z4;
        ((float4*)g_accs)[k] = z4;
    }
    float2 z2 = make_float2(0.f, 0.f);
    for (size_t k = i; k < NS; k += stride) g_s[k] = z2;
}

// ---------------------------------------------------------------------------
// K_qkv: [150000 x 128] @ [128 x 128] + b, packed f32x2 math
// BM=64, BN=128, BK=32, 256 threads, per-thread tile 4x8 (4x4 packed)
// ---------------------------------------------------------------------------
__global__ void __launch_bounds__(256) qkv_kernel(
        const float* __restrict__ x,
        const float* __restrict__ Wq, const float* __restrict__ bq,
        const float* __restrict__ Wk, const float* __restrict__ bk,
        const float* __restrict__ Wv, const float* __restrict__ bv) {
    const float* W; const float* b; float* out;
    if (blockIdx.y == 0)      { W = Wq; b = bq; out = g_q; }
    else if (blockIdx.y == 1) { W = Wk; b = bk; out = g_k; }
    else                      { W = Wv; b = bv; out = g_v; }

    __shared__ float Xs[64][33];
    __shared__ float Ws[32][128];

    const int tid  = threadIdx.x;
    const int m0   = blockIdx.x * 64;
    const int ty   = tid >> 4;
    const int tx   = tid & 15;
    const int row0 = ty * 4;
    const int col0 = tx * 8;

    u64 acc[4][4];
    #pragma unroll
    for (int i = 0; i < 4; i++)
        #pragma unroll
        for (int j = 0; j < 4; j++) acc[i][j] = 0ull;

    for (int kc = 0; kc < 128; kc += 32) {
        #pragma unroll
        for (int l = 0; l < 2; l++) {
            int f4 = tid + l * 256;
            int r  = f4 >> 3;
            int c4 = f4 & 7;
            int grow = m0 + r;
            float4 val = make_float4(0.f, 0.f, 0.f, 0.f);
            if (grow < M_ROWS)
                val = *(const float4*)&x[(size_t)grow * HID + kc + c4 * 4];
            Xs[r][c4 * 4 + 0] = val.x;
            Xs[r][c4 * 4 + 1] = val.y;
            Xs[r][c4 * 4 + 2] = val.z;
            Xs[r][c4 * 4 + 3] = val.w;
        }
        #pragma unroll
        for (int l = 0; l < 4; l++) {
            int f4 = tid + l * 256;
            int r  = f4 >> 5;
            int c4 = f4 & 31;
            *(float4*)&Ws[r][c4 * 4] =
                *(const float4*)&W[(size_t)(kc + r) * HID + c4 * 4];
        }
        __syncthreads();

        #pragma unroll
        for (int k = 0; k < 32; k++) {
            ulonglong2 wb0 = *(const ulonglong2*)&Ws[k][col0];
            ulonglong2 wb1 = *(const ulonglong2*)&Ws[k][col0 + 4];
            #pragma unroll
            for (int i = 0; i < 4; i++) {
                u64 ap = pack2(Xs[row0 + i][k], Xs[row0 + i][k]);
                acc[i][0] = fma2(ap, wb0.x, acc[i][0]);
                acc[i][1] = fma2(ap, wb0.y, acc[i][1]);
                acc[i][2] = fma2(ap, wb1.x, acc[i][2]);
                acc[i][3] = fma2(ap, wb1.y, acc[i][3]);
            }
        }
        __syncthreads();
    }

    #pragma unroll
    for (int i = 0; i < 4; i++) {
        int grow = m0 + row0 + i;
        if (grow < M_ROWS) {
            float o[8];
            #pragma unroll
            for (int j = 0; j < 4; j++) {
                float2 v = unpack2(acc[i][j]);
                o[j * 2]     = v.x + b[col0 + j * 2];
                o[j * 2 + 1] = v.y + b[col0 + j * 2 + 1];
            }
            *(float4*)&out[(size_t)grow * HID + col0]     = make_float4(o[0], o[1], o[2], o[3]);
            *(float4*)&out[(size_t)grow * HID + col0 + 4] = make_float4(o[4], o[5], o[6], o[7]);
        }
    }
}

// ---------------------------------------------------------------------------
// K_edge: fused attention + scatter. One thread = (t_src, edge, head).
// ---------------------------------------------------------------------------
__global__ void __launch_bounds__(256) edge_kernel(const int* __restrict__ ei) {
    const int t_src = blockIdx.y;
    int e = blockIdx.x * 32 + (threadIdx.x >> 3);
    int h = threadIdx.x & 7;
    if (e >= E_PER_T) return;

    int src = ei[(size_t)t_src * 2 * E_PER_T + e];
    int tar = ei[(size_t)t_src * 2 * E_PER_T + E_PER_T + e];

    const float4* kp = (const float4*)(g_k + ((size_t)t_src * N_NODES + src) * HID + h * DK);
    const float4* vp = (const float4*)(g_v + ((size_t)t_src * N_NODES + src) * HID + h * DK);
    float4 kv[4], vv[4];
    #pragma unroll
    for (int i = 0; i < 4; i++) { kv[i] = kp[i]; vv[i] = vp[i]; }

    for (int t_tar = t_src; t_tar < T_WIN; t_tar++) {
        size_t node = (size_t)t_tar * N_NODES + tar;
        const float4* qp = (const float4*)(g_q + node * HID + h * DK);
        float a = 0.0f;
        #pragma unroll
        for (int i = 0; i < 4; i++) {
            float4 qv = qp[i];
            a = fmaf(qv.x, kv[i].x, a);
            a = fmaf(qv.y, kv[i].y, a);
            a = fmaf(qv.z, kv[i].z, a);
            a = fmaf(qv.w, kv[i].w, a);
        }
        a *= 0.25f;                       // 1/sqrt(16)

        float ec = expf(a);
        float es = expf(-a);

        atomicAdd(&g_s[node * NH + h], make_float2(ec, es));

        float* pc = g_accc + node * HID + h * DK;
        float* ps = g_accs + node * HID + h * DK;
        #pragma unroll
        for (int q4 = 0; q4 < 4; q4++) {
            float4 v = vv[q4];
            atomicAdd((float4*)(pc + q4 * 4),
                      make_float4(ec * v.x, ec * v.y, ec * v.z, ec * v.w));
            atomicAdd((float4*)(ps + q4 * 4),
                      make_float4(es * v.x, es * v.y, es * v.z, es * v.w));
        }
    }
}

// ---------------------------------------------------------------------------
// K_ffn v4: one warp = 4 nodes (8 FFN instances). Same dataflow as v3, but
// __launch_bounds__(256, 2) caps regs at 128 -> 2 blocks/SM -> 16 warps/SM
// (latency hiding was the round-3 bottleneck: occ 12.4%, issue 30%).
// ---------------------------------------------------------------------------
__device__ __forceinline__ float gelu_exact(float v) {
    return 0.5f * v * (1.0f + erff(v * 0.70710678118654752f));
}

__device__ __forceinline__ void compute_h(const float* __restrict__ x,
                                          size_t node, int lane,
                                          float hc[4], float hs[4]) {
    size_t off  = node * HID + lane * 4;
    float4 ac = *(const float4*)&g_accc[off];
    float4 as = *(const float4*)&g_accs[off];
    float4 xv = *(const float4*)&x[off];
    float2 sm = g_s[node * NH + (lane >> 2)];
    float ic = 1.0f / (sm.x + 1e-16f);
    float is = 1.0f / (sm.y + 1e-16f);
    hc[0] = fmaf(ac.x, ic, xv.x); hc[1] = fmaf(ac.y, ic, xv.y);
    hc[2] = fmaf(ac.z, ic, xv.z); hc[3] = fmaf(ac.w, ic, xv.w);
    hs[0] = as.x * is; hs[1] = as.y * is; hs[2] = as.z * is; hs[3] = as.w * is;
}

__device__ __forceinline__ void ln_store(const float h[4], int lane,
                                         float4 lns, float4 lnb,
                                         float* __restrict__ dst) {
    float s1 = h[0] + h[1] + h[2] + h[3];
    float s2 = h[0]*h[0] + h[1]*h[1] + h[2]*h[2] + h[3]*h[3];
    #pragma unroll
    for (int o = 16; o > 0; o >>= 1) {
        s1 += __shfl_xor_sync(0xFFFFFFFFu, s1, o);
        s2 += __shfl_xor_sync(0xFFFFFFFFu, s2, o);
    }
    float mu   = s1 * (1.0f / 128.0f);
    float var  = s2 * (1.0f / 128.0f) - mu * mu;
    float rstd = rsqrtf(var + 1e-5f);

    float hn0 = (h[0] - mu) * rstd * lns.x + lnb.x;
    float hn1 = (h[1] - mu) * rstd * lns.y + lnb.y;
    float hn2 = (h[2] - mu) * rstd * lns.z + lnb.z;
    float hn3 = (h[3] - mu) * rstd * lns.w + lnb.w;
    *(float4*)&dst[lane * 4] = make_float4(hn0, hn1, hn2, hn3);
}

__global__ void __launch_bounds__(256, 2) ffn_kernel(
        const float* __restrict__ x,
        const float* __restrict__ ln_s, const float* __restrict__ ln_b,
        const float* __restrict__ W1, const float* __restrict__ b1,
        const float* __restrict__ W2, const float* __restrict__ b2,
        float* __restrict__ out) {
    // per-warp 8KB scratch:
    //   phase1: hn[8][128] floats (first 4KB)
    //   phase2: g[8][256] floats (8KB, aliased; syncwarp separates)
    __shared__ float sbuf[8][2048];

    const int wib  = threadIdx.x >> 5;
    const int lane = threadIdx.x & 31;
    const int wg   = blockIdx.x * 8 + wib;     // warp id over TN/4 = 37500
    if (wg >= TN / 4) return;

    float* hnf = sbuf[wib];
    float* gb  = sbuf[wib];

    const float4 lns = *(const float4*)&ln_s[lane * 4];
    const float4 lnb = *(const float4*)&ln_b[lane * 4];

    // ---- phase 0: h + LayerNorm for 8 instances (f = nn*2 + {c,s})
    #pragma unroll
    for (int nn = 0; nn < 4; nn++) {
        size_t node = (size_t)wg * 4 + nn;
        float hc[4], hs[4];
        compute_h(x, node, lane, hc, hs);
        ln_store(hc, lane, lns, lnb, &hnf[(nn * 2 + 0) * 128]);
        ln_store(hs, lane, lns, lnb, &hnf[(nn * 2 + 1) * 128]);
    }
    __syncwarp();

    // ---- GEMM1: g[f][j] = sum_i hn[f][i] * W1[i][j] + b1[j], j = lane*8..+8
    u64 a1[8][4];
    {
        ulonglong2 bA = *(const ulonglong2*)&b1[lane * 8];
        ulonglong2 bB = *(const ulonglong2*)&b1[lane * 8 + 4];
        #pragma unroll
        for (int f = 0; f < 8; f++) {
            a1[f][0] = bA.x; a1[f][1] = bA.y; a1[f][2] = bB.x; a1[f][3] = bB.y;
        }
    }
    #pragma unroll 1
    for (int i = 0; i < 128; i += 2) {
        const float* w = W1 + (size_t)i * 256 + lane * 8;
        // issue all 4 independent LDG.128 up front (MLP=4)
        ulonglong2 wA0 = *(const ulonglong2*)w;
        ulonglong2 wB0 = *(const ulonglong2*)(w + 4);
        ulonglong2 wA1 = *(const ulonglong2*)(w + 256);
        ulonglong2 wB1 = *(const ulonglong2*)(w + 260);

        #pragma unroll
        for (int f = 0; f < 8; f++) {
            float2 hv = *(const float2*)&hnf[f * 128 + i];
            u64 p0 = pack2(hv.x, hv.x);
            u64 p1 = pack2(hv.y, hv.y);
            a1[f][0] = fma2(p0, wA0.x, a1[f][0]);
            a1[f][1] = fma2(p0, wA0.y, a1[f][1]);
            a1[f][2] = fma2(p0, wB0.x, a1[f][2]);
            a1[f][3] = fma2(p0, wB0.y, a1[f][3]);
            a1[f][0] = fma2(p1, wA1.x, a1[f][0]);
            a1[f][1] = fma2(p1, wA1.y, a1[f][1]);
            a1[f][2] = fma2(p1, wB1.x, a1[f][2]);
            a1[f][3] = fma2(p1, wB1.y, a1[f][3]);
        }
    }
    __syncwarp();   // done reading hnf; gb aliases it

    // ---- GELU, stage g to smem
    #pragma unroll
    for (int f = 0; f < 8; f++) {
        float2 v0 = unpack2(a1[f][0]);
        float2 v1 = unpack2(a1[f][1]);
        float2 v2 = unpack2(a1[f][2]);
        float2 v3 = unpack2(a1[f][3]);
        float* gd = &gb[f * 256 + lane * 8];
        *(float4*)gd       = make_float4(gelu_exact(v0.x), gelu_exact(v0.y),
                                         gelu_exact(v1.x), gelu_exact(v1.y));
        *(float4*)(gd + 4) = make_float4(gelu_exact(v2.x), gelu_exact(v2.y),
                                         gelu_exact(v3.x), gelu_exact(v3.y));
    }
    __syncwarp();

    // ---- GEMM2: r[f][d] = sum_j g[f][j] * W2[j][d] + b2[d], d = lane*4..+4
    u64 a2[8][2];
    {
        ulonglong2 bb = *(const ulonglong2*)&b2[lane * 4];
        #pragma unroll
        for (int f = 0; f < 8; f++) { a2[f][0] = bb.x; a2[f][1] = bb.y; }
    }
    #pragma unroll 1
    for (int j = 0; j < 256; j += 4) {
        const float* w = W2 + (size_t)j * 128 + lane * 4;
        ulonglong2 w0 = *(const ulonglong2*)w;
        ulonglong2 w1 = *(const ulonglong2*)(w + 128);
        ulonglong2 w2v = *(const ulonglong2*)(w + 256);
        ulonglong2 w3v = *(const ulonglong2*)(w + 384);

        #pragma unroll
        for (int f = 0; f < 8; f++) {
            float4 gj = *(const float4*)&gb[f * 256 + j];
            u64 p0 = pack2(gj.x, gj.x);
            u64 p1 = pack2(gj.y, gj.y);
            u64 p2 = pack2(gj.z, gj.z);
            u64 p3 = pack2(gj.w, gj.w);
            a2[f][0] = fma2(p0, w0.x, a2[f][0]);
            a2[f][1] = fma2(p0, w0.y, a2[f][1]);
            a2[f][0] = fma2(p1, w1.x, a2[f][0]);
            a2[f][1] = fma2(p1, w1.y, a2[f][1]);
            a2[f][0] = fma2(p2, w2v.x, a2[f][0]);
            a2[f][1] = fma2(p2, w2v.y, a2[f][1]);
            a2[f][0] = fma2(p3, w3v.x, a2[f][0]);
            a2[f][1] = fma2(p3, w3v.y, a2[f][1]);
        }
    }

    // ---- epilogue: recompute h (L1-hot), residual, write xs/cs/ss
    const size_t S = (size_t)TN * HID;
    #pragma unroll
    for (int nn = 0; nn < 4; nn++) {
        size_t node = (size_t)wg * 4 + nn;
        float hc[4], hs[4];
        compute_h(x, node, lane, hc, hs);

        float2 c01 = unpack2(a2[nn * 2][0]);
        float2 c23 = unpack2(a2[nn * 2][1]);
        float2 s01 = unpack2(a2[nn * 2 + 1][0]);
        float2 s23 = unpack2(a2[nn * 2 + 1][1]);
        float oc[4] = { hc[0] + c01.x, hc[1] + c01.y, hc[2] + c23.x, hc[3] + c23.y };
        float os[4] = { hs[0] + s01.x, hs[1] + s01.y, hs[2] + s23.x, hs[3] + s23.y };

        size_t ob = node * HID + lane * 4;
        *(float4*)&out[ob]       = make_float4(oc[0]+os[0], oc[1]+os[1],
                                               oc[2]+os[2], oc[3]+os[3]);
        *(float4*)&out[S + ob]   = make_float4(oc[0], oc[1], oc[2], oc[3]);
        *(float4*)&out[2*S + ob] = make_float4(os[0], os[1], os[2], os[3]);
    }
}

// ---------------------------------------------------------------------------
// Launch
// ---------------------------------------------------------------------------
extern "C" void kernel_launch(void* const* d_in, const int* in_sizes, int n_in,
                              void* d_out, int out_size) {
    const float* x    = (const float*)d_in[0];
    const int*   ei   = (const int*)  d_in[1];
    const float* Wq   = (const float*)d_in[2];
    const float* bq   = (const float*)d_in[3];
    const float* Wk   = (const float*)d_in[4];
    const float* bk   = (const float*)d_in[5];
    const float* Wv   = (const float*)d_in[6];
    const float* bv   = (const float*)d_in[7];
    const float* ln_s = (const float*)d_in[8];
    const float* ln_b = (const float*)d_in[9];
    const float* W1   = (const float*)d_in[10];
    const float* b1   = (const float*)d_in[11];
    const float* W2   = (const float*)d_in[12];
    const float* b2   = (const float*)d_in[13];
    float* out = (float*)d_out;

    clear_kernel<<<1024, 256>>>();

    qkv_kernel<<<dim3((M_ROWS + 63) / 64, 3), 256>>>(x, Wq, bq, Wk, bk, Wv, bv);

    edge_kernel<<<dim3((E_PER_T + 31) / 32, T_WIN), 256>>>(ei);

    // 37500 warps total (4 nodes each), 8 warps per block
    ffn_kernel<<<(TN / 4 + 7) / 8, 256>>>(x, ln_s, ln_b, W1, b1, W2, b2, out);
}

// round 5
// speedup vs baseline: 2.9558x; 1.0871x over previous
#include <cuda_runtime.h>
#include <math.h>

// ---------------------------------------------------------------------------
// Problem constants
// ---------------------------------------------------------------------------
#define N_NODES 50000
#define T_WIN   3
#define E_PER_T 100000
#define HID     128
#define NH      8
#define DK      16
#define M_ROWS  (T_WIN * N_NODES)          // 150000 rows
#define TN      (T_WIN * N_NODES)

// ---------------------------------------------------------------------------
// Device scratch
// ---------------------------------------------------------------------------
__device__ float g_q[(size_t)M_ROWS * HID];
__device__ float g_k[(size_t)M_ROWS * HID];
__device__ float g_v[(size_t)M_ROWS * HID];
__device__ float g_hc[(size_t)TN * HID];        // normalized causal + residual x
__device__ float g_hs[(size_t)TN * HID];        // normalized spurious
__device__ int   g_cnt[T_WIN * N_NODES];        // histogram, then CSR cursor
__device__ int   g_off[T_WIN * (N_NODES + 1)];  // CSR offsets
__device__ int   g_csr[T_WIN * E_PER_T];        // src node ids, grouped by target

// ---------------------------------------------------------------------------
// Packed fp32x2 helpers (B300 FFMA2 path)
// ---------------------------------------------------------------------------
typedef unsigned long long u64;

__device__ __forceinline__ u64 fma2(u64 a, u64 b, u64 c) {
    u64 d;
    asm("fma.rn.f32x2 %0, %1, %2, %3;" : "=l"(d) : "l"(a), "l"(b), "l"(c));
    return d;
}
__device__ __forceinline__ u64 pack2(float lo, float hi) {
    u64 r;
    asm("mov.b64 %0, {%1, %2};" : "=l"(r) : "f"(lo), "f"(hi));
    return r;
}
__device__ __forceinline__ float2 unpack2(u64 v) {
    float2 f;
    asm("mov.b64 {%0, %1}, %2;" : "=f"(f.x), "=f"(f.y) : "l"(v));
    return f;
}

// ---------------------------------------------------------------------------
// CSR build: zero -> count -> scan -> fill
// ---------------------------------------------------------------------------
__global__ void zero_cnt_kernel() {
    int i = blockIdx.x * blockDim.x + threadIdx.x;
    if (i < T_WIN * N_NODES) g_cnt[i] = 0;
}

__global__ void count_kernel(const int* __restrict__ ei) {
    int g = blockIdx.x * blockDim.x + threadIdx.x;
    if (g >= T_WIN * E_PER_T) return;
    int t   = g / E_PER_T;
    int idx = g - t * E_PER_T;
    int tar = ei[(size_t)t * 2 * E_PER_T + E_PER_T + idx];
    atomicAdd(&g_cnt[t * N_NODES + tar], 1);
}

// One block (1024 thr) per t: exclusive scan of 50000 counts.
__global__ void __launch_bounds__(1024) scan_kernel() {
    const int t    = blockIdx.x;
    const int tid  = threadIdx.x;
    const int lane = tid & 31;
    const int wid  = tid >> 5;
    __shared__ int wsum[32];
    __shared__ int sbase;
    if (tid == 0) sbase = 0;
    __syncthreads();

    for (int c0 = 0; c0 < N_NODES; c0 += 1024) {
        int i = c0 + tid;
        int v = (i < N_NODES) ? g_cnt[t * N_NODES + i] : 0;
        int incl = v;
        #pragma unroll
        for (int o = 1; o < 32; o <<= 1) {
            int u = __shfl_up_sync(0xFFFFFFFFu, incl, o);
            if (lane >= o) incl += u;
        }
        if (lane == 31) wsum[wid] = incl;
        __syncthreads();
        if (wid == 0) {
            int wv = wsum[lane];
            #pragma unroll
            for (int o = 1; o < 32; o <<= 1) {
                int u = __shfl_up_sync(0xFFFFFFFFu, wv, o);
                if (lane >= o) wv += u;
            }
            wsum[lane] = wv;
        }
        __syncthreads();
        int excl = (wid > 0 ? wsum[wid - 1] : 0) + sbase + incl - v;
        if (i < N_NODES) {
            g_off[t * (N_NODES + 1) + i] = excl;
            g_cnt[t * N_NODES + i]       = excl;   // becomes fill cursor
        }
        __syncthreads();
        if (tid == 0) sbase += wsum[31];
        __syncthreads();
    }
    if (tid == 0) g_off[t * (N_NODES + 1) + N_NODES] = sbase;
}

__global__ void fill_kernel(const int* __restrict__ ei) {
    int g = blockIdx.x * blockDim.x + threadIdx.x;
    if (g >= T_WIN * E_PER_T) return;
    int t   = g / E_PER_T;
    int idx = g - t * E_PER_T;
    int src = ei[(size_t)t * 2 * E_PER_T + idx];
    int tar = ei[(size_t)t * 2 * E_PER_T + E_PER_T + idx];
    int pos = atomicAdd(&g_cnt[t * N_NODES + tar], 1);
    g_csr[(size_t)t * E_PER_T + pos] = src;
}

// ---------------------------------------------------------------------------
// K_qkv: [150000 x 128] @ [128 x 128] + b, packed f32x2 math
// ---------------------------------------------------------------------------
__global__ void __launch_bounds__(256) qkv_kernel(
        const float* __restrict__ x,
        const float* __restrict__ Wq, const float* __restrict__ bq,
        const float* __restrict__ Wk, const float* __restrict__ bk,
        const float* __restrict__ Wv, const float* __restrict__ bv) {
    const float* W; const float* b; float* out;
    if (blockIdx.y == 0)      { W = Wq; b = bq; out = g_q; }
    else if (blockIdx.y == 1) { W = Wk; b = bk; out = g_k; }
    else                      { W = Wv; b = bv; out = g_v; }

    __shared__ float Xs[64][33];
    __shared__ float Ws[32][128];

    const int tid  = threadIdx.x;
    const int m0   = blockIdx.x * 64;
    const int ty   = tid >> 4;
    const int tx   = tid & 15;
    const int row0 = ty * 4;
    const int col0 = tx * 8;

    u64 acc[4][4];
    #pragma unroll
    for (int i = 0; i < 4; i++)
        #pragma unroll
        for (int j = 0; j < 4; j++) acc[i][j] = 0ull;

    for (int kc = 0; kc < 128; kc += 32) {
        #pragma unroll
        for (int l = 0; l < 2; l++) {
            int f4 = tid + l * 256;
            int r  = f4 >> 3;
            int c4 = f4 & 7;
            int grow = m0 + r;
            float4 val = make_float4(0.f, 0.f, 0.f, 0.f);
            if (grow < M_ROWS)
                val = *(const float4*)&x[(size_t)grow * HID + kc + c4 * 4];
            Xs[r][c4 * 4 + 0] = val.x;
            Xs[r][c4 * 4 + 1] = val.y;
            Xs[r][c4 * 4 + 2] = val.z;
            Xs[r][c4 * 4 + 3] = val.w;
        }
        #pragma unroll
        for (int l = 0; l < 4; l++) {
            int f4 = tid + l * 256;
            int r  = f4 >> 5;
            int c4 = f4 & 31;
            *(float4*)&Ws[r][c4 * 4] =
                *(const float4*)&W[(size_t)(kc + r) * HID + c4 * 4];
        }
        __syncthreads();

        #pragma unroll
        for (int k = 0; k < 32; k++) {
            ulonglong2 wb0 = *(const ulonglong2*)&Ws[k][col0];
            ulonglong2 wb1 = *(const ulonglong2*)&Ws[k][col0 + 4];
            #pragma unroll
            for (int i = 0; i < 4; i++) {
                u64 ap = pack2(Xs[row0 + i][k], Xs[row0 + i][k]);
                acc[i][0] = fma2(ap, wb0.x, acc[i][0]);
                acc[i][1] = fma2(ap, wb0.y, acc[i][1]);
                acc[i][2] = fma2(ap, wb1.x, acc[i][2]);
                acc[i][3] = fma2(ap, wb1.y, acc[i][3]);
            }
        }
        __syncthreads();
    }

    #pragma unroll
    for (int i = 0; i < 4; i++) {
        int grow = m0 + row0 + i;
        if (grow < M_ROWS) {
            float o[8];
            #pragma unroll
            for (int j = 0; j < 4; j++) {
                float2 v = unpack2(acc[i][j]);
                o[j * 2]     = v.x + b[col0 + j * 2];
                o[j * 2 + 1] = v.y + b[col0 + j * 2 + 1];
            }
            *(float4*)&out[(size_t)grow * HID + col0]     = make_float4(o[0], o[1], o[2], o[3]);
            *(float4*)&out[(size_t)grow * HID + col0 + 4] = make_float4(o[4], o[5], o[6], o[7]);
        }
    }
}

// ---------------------------------------------------------------------------
// K_agg: warp per (t_tar, node). Gather incident edges from CSR, compute
// attention + both softmax aggregations in REGISTERS (no atomics, no clears).
// Lane l holds dims [4l, 4l+4); head = l>>2; per-head dot via 2 quad shuffles.
// Writes h_c = acc_c/sum_c + x  and  h_s = acc_s/sum_s.
// ---------------------------------------------------------------------------
__global__ void __launch_bounds__(256) agg_kernel(const float* __restrict__ x) {
    const int warp = (blockIdx.x * blockDim.x + threadIdx.x) >> 5;
    const int lane = threadIdx.x & 31;
    const int t_tar = blockIdx.y;
    if (warp >= N_NODES) return;
    const int n = warp;

    const size_t rowoff = ((size_t)t_tar * N_NODES + n) * HID + lane * 4;
    const float4 q4 = *(const float4*)&g_q[rowoff];

    float ac0 = 0.f, ac1 = 0.f, ac2 = 0.f, ac3 = 0.f;
    float as0 = 0.f, as1 = 0.f, as2 = 0.f, as3 = 0.f;
    float sc = 0.f, ss = 0.f;

    for (int ts = 0; ts <= t_tar; ts++) {
        const int s0 = g_off[ts * (N_NODES + 1) + n];
        const int s1 = g_off[ts * (N_NODES + 1) + n + 1];
        const int* csr = g_csr + (size_t)ts * E_PER_T;
        const float* kb = g_k + (size_t)ts * N_NODES * HID;
        const float* vb = g_v + (size_t)ts * N_NODES * HID;

        for (int e = s0; e < s1; e++) {
            int src = csr[e];
            size_t so = (size_t)src * HID + lane * 4;
            float4 k4 = *(const float4*)&kb[so];
            float4 v4 = *(const float4*)&vb[so];

            float d = q4.x * k4.x + q4.y * k4.y + q4.z * k4.z + q4.w * k4.w;
            d += __shfl_xor_sync(0xFFFFFFFFu, d, 1);
            d += __shfl_xor_sync(0xFFFFFFFFu, d, 2);
            float a  = d * 0.25f;          // 1/sqrt(16)
            float ec = expf(a);
            float es = expf(-a);
            sc += ec;  ss += es;
            ac0 = fmaf(ec, v4.x, ac0); ac1 = fmaf(ec, v4.y, ac1);
            ac2 = fmaf(ec, v4.z, ac2); ac3 = fmaf(ec, v4.w, ac3);
            as0 = fmaf(es, v4.x, as0); as1 = fmaf(es, v4.y, as1);
            as2 = fmaf(es, v4.z, as2); as3 = fmaf(es, v4.w, as3);
        }
    }

    const float ic = 1.0f / (sc + 1e-16f);
    const float is = 1.0f / (ss + 1e-16f);
    const float4 xv = *(const float4*)&x[rowoff];

    *(float4*)&g_hc[rowoff] = make_float4(fmaf(ac0, ic, xv.x), fmaf(ac1, ic, xv.y),
                                          fmaf(ac2, ic, xv.z), fmaf(ac3, ic, xv.w));
    *(float4*)&g_hs[rowoff] = make_float4(as0 * is, as1 * is, as2 * is, as3 * is);
}

// ---------------------------------------------------------------------------
// K_ffn: one warp = 4 nodes (8 FFN instances), f32x2 packed math,
// __launch_bounds__(256,2) for 128-reg / 2-blocks-per-SM occupancy.
// Inputs g_hc/g_hs already normalized + residual-added.
// ---------------------------------------------------------------------------
__device__ __forceinline__ float gelu_exact(float v) {
    return 0.5f * v * (1.0f + erff(v * 0.70710678118654752f));
}

__device__ __forceinline__ void ln_store4(float4 h4, int lane,
                                          float4 lns, float4 lnb,
                                          float* __restrict__ dst) {
    float s1 = h4.x + h4.y + h4.z + h4.w;
    float s2 = h4.x*h4.x + h4.y*h4.y + h4.z*h4.z + h4.w*h4.w;
    #pragma unroll
    for (int o = 16; o > 0; o >>= 1) {
        s1 += __shfl_xor_sync(0xFFFFFFFFu, s1, o);
        s2 += __shfl_xor_sync(0xFFFFFFFFu, s2, o);
    }
    float mu   = s1 * (1.0f / 128.0f);
    float var  = s2 * (1.0f / 128.0f) - mu * mu;
    float rstd = rsqrtf(var + 1e-5f);

    *(float4*)&dst[lane * 4] = make_float4(
        (h4.x - mu) * rstd * lns.x + lnb.x,
        (h4.y - mu) * rstd * lns.y + lnb.y,
        (h4.z - mu) * rstd * lns.z + lnb.z,
        (h4.w - mu) * rstd * lns.w + lnb.w);
}

__global__ void __launch_bounds__(256, 2) ffn_kernel(
        const float* __restrict__ ln_s, const float* __restrict__ ln_b,
        const float* __restrict__ W1, const float* __restrict__ b1,
        const float* __restrict__ W2, const float* __restrict__ b2,
        float* __restrict__ out) {
    __shared__ float sbuf[8][2048];

    const int wib  = threadIdx.x >> 5;
    const int lane = threadIdx.x & 31;
    const int wg   = blockIdx.x * 8 + wib;     // warp id over TN/4 = 37500
    if (wg >= TN / 4) return;

    float* hnf = sbuf[wib];
    float* gb  = sbuf[wib];

    const float4 lns = *(const float4*)&ln_s[lane * 4];
    const float4 lnb = *(const float4*)&ln_b[lane * 4];

    // ---- phase 0: LayerNorm for 8 instances (f = nn*2 + {c,s})
    #pragma unroll
    for (int nn = 0; nn < 4; nn++) {
        size_t off = ((size_t)wg * 4 + nn) * HID + lane * 4;
        float4 c4 = *(const float4*)&g_hc[off];
        float4 s4 = *(const float4*)&g_hs[off];
        ln_store4(c4, lane, lns, lnb, &hnf[(nn * 2 + 0) * 128]);
        ln_store4(s4, lane, lns, lnb, &hnf[(nn * 2 + 1) * 128]);
    }
    __syncwarp();

    // ---- GEMM1: g[f][j] = sum_i hn[f][i] * W1[i][j] + b1[j], j = lane*8..+8
    u64 a1[8][4];
    {
        ulonglong2 bA = *(const ulonglong2*)&b1[lane * 8];
        ulonglong2 bB = *(const ulonglong2*)&b1[lane * 8 + 4];
        #pragma unroll
        for (int f = 0; f < 8; f++) {
            a1[f][0] = bA.x; a1[f][1] = bA.y; a1[f][2] = bB.x; a1[f][3] = bB.y;
        }
    }
    #pragma unroll 1
    for (int i = 0; i < 128; i += 2) {
        const float* w = W1 + (size_t)i * 256 + lane * 8;
        ulonglong2 wA0 = *(const ulonglong2*)w;
        ulonglong2 wB0 = *(const ulonglong2*)(w + 4);
        ulonglong2 wA1 = *(const ulonglong2*)(w + 256);
        ulonglong2 wB1 = *(const ulonglong2*)(w + 260);

        #pragma unroll
        for (int f = 0; f < 8; f++) {
            float2 hv = *(const float2*)&hnf[f * 128 + i];
            u64 p0 = pack2(hv.x, hv.x);
            u64 p1 = pack2(hv.y, hv.y);
            a1[f][0] = fma2(p0, wA0.x, a1[f][0]);
            a1[f][1] = fma2(p0, wA0.y, a1[f][1]);
            a1[f][2] = fma2(p0, wB0.x, a1[f][2]);
            a1[f][3] = fma2(p0, wB0.y, a1[f][3]);
            a1[f][0] = fma2(p1, wA1.x, a1[f][0]);
            a1[f][1] = fma2(p1, wA1.y, a1[f][1]);
            a1[f][2] = fma2(p1, wB1.x, a1[f][2]);
            a1[f][3] = fma2(p1, wB1.y, a1[f][3]);
        }
    }
    __syncwarp();   // done reading hnf; gb aliases it

    // ---- GELU, stage g to smem
    #pragma unroll
    for (int f = 0; f < 8; f++) {
        float2 v0 = unpack2(a1[f][0]);
        float2 v1 = unpack2(a1[f][1]);
        float2 v2 = unpack2(a1[f][2]);
        float2 v3 = unpack2(a1[f][3]);
        float* gd = &gb[f * 256 + lane * 8];
        *(float4*)gd       = make_float4(gelu_exact(v0.x), gelu_exact(v0.y),
                                         gelu_exact(v1.x), gelu_exact(v1.y));
        *(float4*)(gd + 4) = make_float4(gelu_exact(v2.x), gelu_exact(v2.y),
                                         gelu_exact(v3.x), gelu_exact(v3.y));
    }
    __syncwarp();

    // ---- GEMM2: r[f][d] = sum_j g[f][j] * W2[j][d] + b2[d], d = lane*4..+4
    u64 a2[8][2];
    {
        ulonglong2 bb = *(const ulonglong2*)&b2[lane * 4];
        #pragma unroll
        for (int f = 0; f < 8; f++) { a2[f][0] = bb.x; a2[f][1] = bb.y; }
    }
    #pragma unroll 1
    for (int j = 0; j < 256; j += 4) {
        const float* w = W2 + (size_t)j * 128 + lane * 4;
        ulonglong2 w0  = *(const ulonglong2*)w;
        ulonglong2 w1  = *(const ulonglong2*)(w + 128);
        ulonglong2 w2v = *(const ulonglong2*)(w + 256);
        ulonglong2 w3v = *(const ulonglong2*)(w + 384);

        #pragma unroll
        for (int f = 0; f < 8; f++) {
            float4 gj = *(const float4*)&gb[f * 256 + j];
            u64 p0 = pack2(gj.x, gj.x);
            u64 p1 = pack2(gj.y, gj.y);
            u64 p2 = pack2(gj.z, gj.z);
            u64 p3 = pack2(gj.w, gj.w);
            a2[f][0] = fma2(p0, w0.x, a2[f][0]);
            a2[f][1] = fma2(p0, w0.y, a2[f][1]);
            a2[f][0] = fma2(p1, w1.x, a2[f][0]);
            a2[f][1] = fma2(p1, w1.y, a2[f][1]);
            a2[f][0] = fma2(p2, w2v.x, a2[f][0]);
            a2[f][1] = fma2(p2, w2v.y, a2[f][1]);
            a2[f][0] = fma2(p3, w3v.x, a2[f][0]);
            a2[f][1] = fma2(p3, w3v.y, a2[f][1]);
        }
    }

    // ---- epilogue: residual (reload h, L1/L2-hot), write xs/cs/ss
    const size_t S = (size_t)TN * HID;
    #pragma unroll
    for (int nn = 0; nn < 4; nn++) {
        size_t off = ((size_t)wg * 4 + nn) * HID + lane * 4;
        float4 c4 = *(const float4*)&g_hc[off];
        float4 s4 = *(const float4*)&g_hs[off];

        float2 c01 = unpack2(a2[nn * 2][0]);
        float2 c23 = unpack2(a2[nn * 2][1]);
        float2 s01 = unpack2(a2[nn * 2 + 1][0]);
        float2 s23 = unpack2(a2[nn * 2 + 1][1]);
        float oc[4] = { c4.x + c01.x, c4.y + c01.y, c4.z + c23.x, c4.w + c23.y };
        float os[4] = { s4.x + s01.x, s4.y + s01.y, s4.z + s23.x, s4.w + s23.y };

        *(float4*)&out[off]         = make_float4(oc[0]+os[0], oc[1]+os[1],
                                                  oc[2]+os[2], oc[3]+os[3]);
        *(float4*)&out[S + off]     = make_float4(oc[0], oc[1], oc[2], oc[3]);
        *(float4*)&out[2*S + off]   = make_float4(os[0], os[1], os[2], os[3]);
    }
}

// ---------------------------------------------------------------------------
// Launch
// ---------------------------------------------------------------------------
extern "C" void kernel_launch(void* const* d_in, const int* in_sizes, int n_in,
                              void* d_out, int out_size) {
    const float* x    = (const float*)d_in[0];
    const int*   ei   = (const int*)  d_in[1];
    const float* Wq   = (const float*)d_in[2];
    const float* bq   = (const float*)d_in[3];
    const float* Wk   = (const float*)d_in[4];
    const float* bk   = (const float*)d_in[5];
    const float* Wv   = (const float*)d_in[6];
    const float* bv   = (const float*)d_in[7];
    const float* ln_s = (const float*)d_in[8];
    const float* ln_b = (const float*)d_in[9];
    const float* W1   = (const float*)d_in[10];
    const float* b1   = (const float*)d_in[11];
    const float* W2   = (const float*)d_in[12];
    const float* b2   = (const float*)d_in[13];
    float* out = (float*)d_out;

    // CSR build (depends only on edge_index)
    zero_cnt_kernel<<<(T_WIN * N_NODES + 255) / 256, 256>>>();
    count_kernel<<<(T_WIN * E_PER_T + 255) / 256, 256>>>(ei);
    scan_kernel<<<T_WIN, 1024>>>();
    fill_kernel<<<(T_WIN * E_PER_T + 255) / 256, 256>>>(ei);

    // QKV projections
    qkv_kernel<<<dim3((M_ROWS + 63) / 64, 3), 256>>>(x, Wq, bq, Wk, bk, Wv, bv);

    // Gather-aggregate (replaces scatter + clears)
    agg_kernel<<<dim3((N_NODES * 32 + 255) / 256, T_WIN), 256>>>(x);

    // Dual FFN
    ffn_kernel<<<(TN / 4 + 7) / 8, 256>>>(ln_s, ln_b, W1, b1, W2, b2, out);
}

// round 6
// speedup vs baseline: 2.9855x; 1.0100x over previous
#include <cuda_runtime.h>
#include <math.h>

// ---------------------------------------------------------------------------
// Problem constants
// ---------------------------------------------------------------------------
#define N_NODES 50000
#define T_WIN   3
#define E_PER_T 100000
#define HID     128
#define NH      8
#define DK      16
#define M_ROWS  (T_WIN * N_NODES)          // 150000 rows
#define TN      (T_WIN * N_NODES)

// ---------------------------------------------------------------------------
// Device scratch
// ---------------------------------------------------------------------------
__device__ float g_q[(size_t)M_ROWS * HID];
__device__ float g_k[(size_t)M_ROWS * HID];
__device__ float g_v[(size_t)M_ROWS * HID];
__device__ float g_hc[(size_t)TN * HID];        // normalized causal + residual x
__device__ float g_hs[(size_t)TN * HID];        // normalized spurious
__device__ int   g_cnt[T_WIN * N_NODES];        // histogram, then CSR cursor
__device__ int   g_off[T_WIN * (N_NODES + 1)];  // CSR offsets
__device__ int   g_csr[T_WIN * E_PER_T];        // src node ids, grouped by target

// ---------------------------------------------------------------------------
// Packed fp32x2 helpers (B300 FFMA2 path)
// ---------------------------------------------------------------------------
typedef unsigned long long u64;

__device__ __forceinline__ u64 fma2(u64 a, u64 b, u64 c) {
    u64 d;
    asm("fma.rn.f32x2 %0, %1, %2, %3;" : "=l"(d) : "l"(a), "l"(b), "l"(c));
    return d;
}
__device__ __forceinline__ u64 pack2(float lo, float hi) {
    u64 r;
    asm("mov.b64 %0, {%1, %2};" : "=l"(r) : "f"(lo), "f"(hi));
    return r;
}
__device__ __forceinline__ float2 unpack2(u64 v) {
    float2 f;
    asm("mov.b64 {%0, %1}, %2;" : "=f"(f.x), "=f"(f.y) : "l"(v));
    return f;
}

// cp.async 16B
__device__ __forceinline__ void cp16(void* sdst, const void* gsrc) {
    unsigned sa = (unsigned)__cvta_generic_to_shared(sdst);
    asm volatile("cp.async.ca.shared.global [%0], [%1], 16;\n"
                 :: "r"(sa), "l"(gsrc) : "memory");
}
__device__ __forceinline__ void cp_commit() {
    asm volatile("cp.async.commit_group;\n" ::: "memory");
}

// ---------------------------------------------------------------------------
// CSR build: zero -> count -> scan -> fill
// ---------------------------------------------------------------------------
__global__ void zero_cnt_kernel() {
    int i = blockIdx.x * blockDim.x + threadIdx.x;
    if (i < T_WIN * N_NODES) g_cnt[i] = 0;
}

__global__ void count_kernel(const int* __restrict__ ei) {
    int g = blockIdx.x * blockDim.x + threadIdx.x;
    if (g >= T_WIN * E_PER_T) return;
    int t   = g / E_PER_T;
    int idx = g - t * E_PER_T;
    int tar = ei[(size_t)t * 2 * E_PER_T + E_PER_T + idx];
    atomicAdd(&g_cnt[t * N_NODES + tar], 1);
}

// One block (1024 thr) per t: exclusive scan of 50000 counts.
__global__ void __launch_bounds__(1024) scan_kernel() {
    const int t    = blockIdx.x;
    const int tid  = threadIdx.x;
    const int lane = tid & 31;
    const int wid  = tid >> 5;
    __shared__ int wsum[32];
    __shared__ int sbase;
    if (tid == 0) sbase = 0;
    __syncthreads();

    for (int c0 = 0; c0 < N_NODES; c0 += 1024) {
        int i = c0 + tid;
        int v = (i < N_NODES) ? g_cnt[t * N_NODES + i] : 0;
        int incl = v;
        #pragma unroll
        for (int o = 1; o < 32; o <<= 1) {
            int u = __shfl_up_sync(0xFFFFFFFFu, incl, o);
            if (lane >= o) incl += u;
        }
        if (lane == 31) wsum[wid] = incl;
        __syncthreads();
        if (wid == 0) {
            int wv = wsum[lane];
            #pragma unroll
            for (int o = 1; o < 32; o <<= 1) {
                int u = __shfl_up_sync(0xFFFFFFFFu, wv, o);
                if (lane >= o) wv += u;
            }
            wsum[lane] = wv;
        }
        __syncthreads();
        int excl = (wid > 0 ? wsum[wid - 1] : 0) + sbase + incl - v;
        if (i < N_NODES) {
            g_off[t * (N_NODES + 1) + i] = excl;
            g_cnt[t * N_NODES + i]       = excl;   // becomes fill cursor
        }
        __syncthreads();
        if (tid == 0) sbase += wsum[31];
        __syncthreads();
    }
    if (tid == 0) g_off[t * (N_NODES + 1) + N_NODES] = sbase;
}

__global__ void fill_kernel(const int* __restrict__ ei) {
    int g = blockIdx.x * blockDim.x + threadIdx.x;
    if (g >= T_WIN * E_PER_T) return;
    int t   = g / E_PER_T;
    int idx = g - t * E_PER_T;
    int src = ei[(size_t)t * 2 * E_PER_T + idx];
    int tar = ei[(size_t)t * 2 * E_PER_T + E_PER_T + idx];
    int pos = atomicAdd(&g_cnt[t * N_NODES + tar], 1);
    g_csr[(size_t)t * E_PER_T + pos] = src;
}

// ---------------------------------------------------------------------------
// K_qkv: [150000 x 128] @ [128 x 128] + b, packed f32x2 math
// ---------------------------------------------------------------------------
__global__ void __launch_bounds__(256) qkv_kernel(
        const float* __restrict__ x,
        const float* __restrict__ Wq, const float* __restrict__ bq,
        const float* __restrict__ Wk, const float* __restrict__ bk,
        const float* __restrict__ Wv, const float* __restrict__ bv) {
    const float* W; const float* b; float* out;
    if (blockIdx.y == 0)      { W = Wq; b = bq; out = g_q; }
    else if (blockIdx.y == 1) { W = Wk; b = bk; out = g_k; }
    else                      { W = Wv; b = bv; out = g_v; }

    __shared__ float Xs[64][33];
    __shared__ float Ws[32][128];

    const int tid  = threadIdx.x;
    const int m0   = blockIdx.x * 64;
    const int ty   = tid >> 4;
    const int tx   = tid & 15;
    const int row0 = ty * 4;
    const int col0 = tx * 8;

    u64 acc[4][4];
    #pragma unroll
    for (int i = 0; i < 4; i++)
        #pragma unroll
        for (int j = 0; j < 4; j++) acc[i][j] = 0ull;

    for (int kc = 0; kc < 128; kc += 32) {
        #pragma unroll
        for (int l = 0; l < 2; l++) {
            int f4 = tid + l * 256;
            int r  = f4 >> 3;
            int c4 = f4 & 7;
            int grow = m0 + r;
            float4 val = make_float4(0.f, 0.f, 0.f, 0.f);
            if (grow < M_ROWS)
                val = *(const float4*)&x[(size_t)grow * HID + kc + c4 * 4];
            Xs[r][c4 * 4 + 0] = val.x;
            Xs[r][c4 * 4 + 1] = val.y;
            Xs[r][c4 * 4 + 2] = val.z;
            Xs[r][c4 * 4 + 3] = val.w;
        }
        #pragma unroll
        for (int l = 0; l < 4; l++) {
            int f4 = tid + l * 256;
            int r  = f4 >> 5;
            int c4 = f4 & 31;
            *(float4*)&Ws[r][c4 * 4] =
                *(const float4*)&W[(size_t)(kc + r) * HID + c4 * 4];
        }
        __syncthreads();

        #pragma unroll
        for (int k = 0; k < 32; k++) {
            ulonglong2 wb0 = *(const ulonglong2*)&Ws[k][col0];
            ulonglong2 wb1 = *(const ulonglong2*)&Ws[k][col0 + 4];
            #pragma unroll
            for (int i = 0; i < 4; i++) {
                u64 ap = pack2(Xs[row0 + i][k], Xs[row0 + i][k]);
                acc[i][0] = fma2(ap, wb0.x, acc[i][0]);
                acc[i][1] = fma2(ap, wb0.y, acc[i][1]);
                acc[i][2] = fma2(ap, wb1.x, acc[i][2]);
                acc[i][3] = fma2(ap, wb1.y, acc[i][3]);
            }
        }
        __syncthreads();
    }

    #pragma unroll
    for (int i = 0; i < 4; i++) {
        int grow = m0 + row0 + i;
        if (grow < M_ROWS) {
            float o[8];
            #pragma unroll
            for (int j = 0; j < 4; j++) {
                float2 v = unpack2(acc[i][j]);
                o[j * 2]     = v.x + b[col0 + j * 2];
                o[j * 2 + 1] = v.y + b[col0 + j * 2 + 1];
            }
            *(float4*)&out[(size_t)grow * HID + col0]     = make_float4(o[0], o[1], o[2], o[3]);
            *(float4*)&out[(size_t)grow * HID + col0 + 4] = make_float4(o[4], o[5], o[6], o[7]);
        }
    }
}

// ---------------------------------------------------------------------------
// K_agg: warp per (t_tar, node). CSR gather; attention + dual softmax
// aggregation in registers.
// ---------------------------------------------------------------------------
__global__ void __launch_bounds__(256) agg_kernel(const float* __restrict__ x) {
    const int warp = (blockIdx.x * blockDim.x + threadIdx.x) >> 5;
    const int lane = threadIdx.x & 31;
    const int t_tar = blockIdx.y;
    if (warp >= N_NODES) return;
    const int n = warp;

    const size_t rowoff = ((size_t)t_tar * N_NODES + n) * HID + lane * 4;
    const float4 q4 = *(const float4*)&g_q[rowoff];

    float ac0 = 0.f, ac1 = 0.f, ac2 = 0.f, ac3 = 0.f;
    float as0 = 0.f, as1 = 0.f, as2 = 0.f, as3 = 0.f;
    float sc = 0.f, ss = 0.f;

    for (int ts = 0; ts <= t_tar; ts++) {
        const int s0 = g_off[ts * (N_NODES + 1) + n];
        const int s1 = g_off[ts * (N_NODES + 1) + n + 1];
        const int* csr = g_csr + (size_t)ts * E_PER_T;
        const float* kb = g_k + (size_t)ts * N_NODES * HID;
        const float* vb = g_v + (size_t)ts * N_NODES * HID;

        for (int e = s0; e < s1; e++) {
            int src = csr[e];
            size_t so = (size_t)src * HID + lane * 4;
            float4 k4 = *(const float4*)&kb[so];
            float4 v4 = *(const float4*)&vb[so];

            float d = q4.x * k4.x + q4.y * k4.y + q4.z * k4.z + q4.w * k4.w;
            d += __shfl_xor_sync(0xFFFFFFFFu, d, 1);
            d += __shfl_xor_sync(0xFFFFFFFFu, d, 2);
            float a  = d * 0.25f;          // 1/sqrt(16)
            float ec = expf(a);
            float es = expf(-a);
            sc += ec;  ss += es;
            ac0 = fmaf(ec, v4.x, ac0); ac1 = fmaf(ec, v4.y, ac1);
            ac2 = fmaf(ec, v4.z, ac2); ac3 = fmaf(ec, v4.w, ac3);
            as0 = fmaf(es, v4.x, as0); as1 = fmaf(es, v4.y, as1);
            as2 = fmaf(es, v4.z, as2); as3 = fmaf(es, v4.w, as3);
        }
    }

    const float ic = 1.0f / (sc + 1e-16f);
    const float is = 1.0f / (ss + 1e-16f);
    const float4 xv = *(const float4*)&x[rowoff];

    *(float4*)&g_hc[rowoff] = make_float4(fmaf(ac0, ic, xv.x), fmaf(ac1, ic, xv.y),
                                          fmaf(ac2, ic, xv.z), fmaf(ac3, ic, xv.w));
    *(float4*)&g_hs[rowoff] = make_float4(as0 * is, as1 * is, as2 * is, as3 * is);
}

// ---------------------------------------------------------------------------
// K_ffn v5: warp = 4 nodes (8 instances), f32x2 packed math, 2 blocks/SM.
// W1/W2 staged block-cooperatively into smem via cp.async double buffer
// (removes per-warp W LDG streams -> no L2-miss stalls; traffic /8).
// Lane owns j-cols {lane*4..+4, 128+lane*4..+4} (GEMM1) -> conflict-free LDS.
// ---------------------------------------------------------------------------
__device__ __forceinline__ float gelu_exact(float v) {
    return 0.5f * v * (1.0f + erff(v * 0.70710678118654752f));
}

__device__ __forceinline__ void ln_store4(float4 h4, int lane,
                                          float4 lns, float4 lnb,
                                          float* __restrict__ dst) {
    float s1 = h4.x + h4.y + h4.z + h4.w;
    float s2 = h4.x*h4.x + h4.y*h4.y + h4.z*h4.z + h4.w*h4.w;
    #pragma unroll
    for (int o = 16; o > 0; o >>= 1) {
        s1 += __shfl_xor_sync(0xFFFFFFFFu, s1, o);
        s2 += __shfl_xor_sync(0xFFFFFFFFu, s2, o);
    }
    float mu   = s1 * (1.0f / 128.0f);
    float var  = s2 * (1.0f / 128.0f) - mu * mu;
    float rstd = rsqrtf(var + 1e-5f);

    *(float4*)&dst[lane * 4] = make_float4(
        (h4.x - mu) * rstd * lns.x + lnb.x,
        (h4.y - mu) * rstd * lns.y + lnb.y,
        (h4.z - mu) * rstd * lns.z + lnb.z,
        (h4.w - mu) * rstd * lns.w + lnb.w);
}

__global__ void __launch_bounds__(256, 2) ffn_kernel(
        const float* __restrict__ ln_s, const float* __restrict__ ln_b,
        const float* __restrict__ W1, const float* __restrict__ b1,
        const float* __restrict__ W2, const float* __restrict__ b2,
        float* __restrict__ out) {
    __shared__ float sbuf[8][2048];                    // 64 KB per-warp hn/g
    __shared__ __align__(16) float ws[2][4096];        // 32 KB W stage (db)

    const int tid  = threadIdx.x;
    const int wib  = tid >> 5;
    const int lane = tid & 31;
    const int wg   = blockIdx.x * 8 + wib;     // warp id over TN/4 = 37500
    const bool active = (wg < TN / 4);

    float* hnf = sbuf[wib];
    float* gb  = sbuf[wib];

    const float4 lns = active ? *(const float4*)&ln_s[lane * 4] : make_float4(0,0,0,0);
    const float4 lnb = active ? *(const float4*)&ln_b[lane * 4] : make_float4(0,0,0,0);

    // ---- kick off stage of W1 chunk 0 (16 rows x 256 = 16 KB)
    {
        const float4* g4 = (const float4*)W1;
        #pragma unroll
        for (int t = 0; t < 4; t++)
            cp16(&ws[0][(tid + t * 256) * 4], &g4[tid + t * 256]);
        cp_commit();
    }

    // ---- phase 0: LayerNorm for 8 instances (f = nn*2 + {c,s})
    if (active) {
        #pragma unroll
        for (int nn = 0; nn < 4; nn++) {
            size_t off = ((size_t)wg * 4 + nn) * HID + lane * 4;
            float4 c4 = *(const float4*)&g_hc[off];
            float4 s4 = *(const float4*)&g_hs[off];
            ln_store4(c4, lane, lns, lnb, &hnf[(nn * 2 + 0) * 128]);
            ln_store4(s4, lane, lns, lnb, &hnf[(nn * 2 + 1) * 128]);
        }
    }
    __syncwarp();

    // ---- GEMM1: g[f][j] = sum_i hn[f][i]*W1[i][j] + b1[j]
    //      lane owns j in {lane*4..+4} and {128+lane*4..+4}
    u64 a1[8][4];
    {
        ulonglong2 bA = *(const ulonglong2*)&b1[lane * 4];
        ulonglong2 bB = *(const ulonglong2*)&b1[128 + lane * 4];
        #pragma unroll
        for (int f = 0; f < 8; f++) {
            a1[f][0] = bA.x; a1[f][1] = bA.y; a1[f][2] = bB.x; a1[f][3] = bB.y;
        }
    }
    #pragma unroll 1
    for (int c = 0; c < 8; c++) {
        // stage next chunk while computing this one
        if (c < 7) {
            const float4* g4 = (const float4*)(W1 + (size_t)(c + 1) * 16 * 256);
            #pragma unroll
            for (int t = 0; t < 4; t++)
                cp16(&ws[(c + 1) & 1][(tid + t * 256) * 4], &g4[tid + t * 256]);
            cp_commit();
            asm volatile("cp.async.wait_group 1;\n" ::: "memory");
        } else {
            asm volatile("cp.async.wait_group 0;\n" ::: "memory");
        }
        __syncthreads();

        const float* wsb = ws[c & 1];
        #pragma unroll 1
        for (int ii = 0; ii < 16; ii += 2) {
            ulonglong2 wA0 = *(const ulonglong2*)&wsb[ii * 256 + lane * 4];
            ulonglong2 wB0 = *(const ulonglong2*)&wsb[ii * 256 + 128 + lane * 4];
            ulonglong2 wA1 = *(const ulonglong2*)&wsb[(ii + 1) * 256 + lane * 4];
            ulonglong2 wB1 = *(const ulonglong2*)&wsb[(ii + 1) * 256 + 128 + lane * 4];
            const int i = c * 16 + ii;

            #pragma unroll
            for (int f = 0; f < 8; f++) {
                float2 hv = *(const float2*)&hnf[f * 128 + i];
                u64 p0 = pack2(hv.x, hv.x);
                u64 p1 = pack2(hv.y, hv.y);
                a1[f][0] = fma2(p0, wA0.x, a1[f][0]);
                a1[f][1] = fma2(p0, wA0.y, a1[f][1]);
                a1[f][2] = fma2(p0, wB0.x, a1[f][2]);
                a1[f][3] = fma2(p0, wB0.y, a1[f][3]);
                a1[f][0] = fma2(p1, wA1.x, a1[f][0]);
                a1[f][1] = fma2(p1, wA1.y, a1[f][1]);
                a1[f][2] = fma2(p1, wB1.x, a1[f][2]);
                a1[f][3] = fma2(p1, wB1.y, a1[f][3]);
            }
        }
        __syncthreads();
    }

    // ---- kick off stage of W2 chunk 0 (32 rows x 128 = 16 KB)
    {
        const float4* g4 = (const float4*)W2;
        #pragma unroll
        for (int t = 0; t < 4; t++)
            cp16(&ws[0][(tid + t * 256) * 4], &g4[tid + t * 256]);
        cp_commit();
    }

    // ---- GELU, stage g to smem (logical cols lane*4 and 128+lane*4)
    #pragma unroll
    for (int f = 0; f < 8; f++) {
        float2 v0 = unpack2(a1[f][0]);
        float2 v1 = unpack2(a1[f][1]);
        float2 v2 = unpack2(a1[f][2]);
        float2 v3 = unpack2(a1[f][3]);
        *(float4*)&gb[f * 256 + lane * 4] =
            make_float4(gelu_exact(v0.x), gelu_exact(v0.y),
                        gelu_exact(v1.x), gelu_exact(v1.y));
        *(float4*)&gb[f * 256 + 128 + lane * 4] =
            make_float4(gelu_exact(v2.x), gelu_exact(v2.y),
                        gelu_exact(v3.x), gelu_exact(v3.y));
    }
    __syncwarp();

    // ---- GEMM2: r[f][d] = sum_j g[f][j]*W2[j][d] + b2[d], d = lane*4..+4
    u64 a2[8][2];
    {
        ulonglong2 bb = *(const ulonglong2*)&b2[lane * 4];
        #pragma unroll
        for (int f = 0; f < 8; f++) { a2[f][0] = bb.x; a2[f][1] = bb.y; }
    }
    #pragma unroll 1
    for (int c = 0; c < 8; c++) {
        if (c < 7) {
            const float4* g4 = (const float4*)(W2 + (size_t)(c + 1) * 32 * 128);
            #pragma unroll
            for (int t = 0; t < 4; t++)
                cp16(&ws[(c + 1) & 1][(tid + t * 256) * 4], &g4[tid + t * 256]);
            cp_commit();
            asm volatile("cp.async.wait_group 1;\n" ::: "memory");
        } else {
            asm volatile("cp.async.wait_group 0;\n" ::: "memory");
        }
        __syncthreads();

        const float* wsb = ws[c & 1];
        #pragma unroll 1
        for (int jj = 0; jj < 32; jj += 4) {
            ulonglong2 w0  = *(const ulonglong2*)&wsb[(jj + 0) * 128 + lane * 4];
            ulonglong2 w1  = *(const ulonglong2*)&wsb[(jj + 1) * 128 + lane * 4];
            ulonglong2 w2v = *(const ulonglong2*)&wsb[(jj + 2) * 128 + lane * 4];
            ulonglong2 w3v = *(const ulonglong2*)&wsb[(jj + 3) * 128 + lane * 4];
            const int j = c * 32 + jj;

            #pragma unroll
            for (int f = 0; f < 8; f++) {
                float4 gj = *(const float4*)&gb[f * 256 + j];
                u64 p0 = pack2(gj.x, gj.x);
                u64 p1 = pack2(gj.y, gj.y);
                u64 p2 = pack2(gj.z, gj.z);
                u64 p3 = pack2(gj.w, gj.w);
                a2[f][0] = fma2(p0, w0.x, a2[f][0]);
                a2[f][1] = fma2(p0, w0.y, a2[f][1]);
                a2[f][0] = fma2(p1, w1.x, a2[f][0]);
                a2[f][1] = fma2(p1, w1.y, a2[f][1]);
                a2[f][0] = fma2(p2, w2v.x, a2[f][0]);
                a2[f][1] = fma2(p2, w2v.y, a2[f][1]);
                a2[f][0] = fma2(p3, w3v.x, a2[f][0]);
                a2[f][1] = fma2(p3, w3v.y, a2[f][1]);
            }
        }
        __syncthreads();
    }

    if (!active) return;

    // ---- epilogue: residual (reload h, L2-hot), write xs/cs/ss
    const size_t S = (size_t)TN * HID;
    #pragma unroll
    for (int nn = 0; nn < 4; nn++) {
        size_t off = ((size_t)wg * 4 + nn) * HID + lane * 4;
        float4 c4 = *(const float4*)&g_hc[off];
        float4 s4 = *(const float4*)&g_hs[off];

        float2 c01 = unpack2(a2[nn * 2][0]);
        float2 c23 = unpack2(a2[nn * 2][1]);
        float2 s01 = unpack2(a2[nn * 2 + 1][0]);
        float2 s23 = unpack2(a2[nn * 2 + 1][1]);
        float oc[4] = { c4.x + c01.x, c4.y + c01.y, c4.z + c23.x, c4.w + c23.y };
        float os[4] = { s4.x + s01.x, s4.y + s01.y, s4.z + s23.x, s4.w + s23.y };

        *(float4*)&out[off]         = make_float4(oc[0]+os[0], oc[1]+os[1],
                                                  oc[2]+os[2], oc[3]+os[3]);
        *(float4*)&out[S + off]     = make_float4(oc[0], oc[1], oc[2], oc[3]);
        *(float4*)&out[2*S + off]   = make_float4(os[0], os[1], os[2], os[3]);
    }
}

// ---------------------------------------------------------------------------
// Launch
// ---------------------------------------------------------------------------
extern "C" void kernel_launch(void* const* d_in, const int* in_sizes, int n_in,
                              void* d_out, int out_size) {
    const float* x    = (const float*)d_in[0];
    const int*   ei   = (const int*)  d_in[1];
    const float* Wq   = (const float*)d_in[2];
    const float* bq   = (const float*)d_in[3];
    const float* Wk   = (const float*)d_in[4];
    const float* bk   = (const float*)d_in[5];
    const float* Wv   = (const float*)d_in[6];
    const float* bv   = (const float*)d_in[7];
    const float* ln_s = (const float*)d_in[8];
    const float* ln_b = (const float*)d_in[9];
    const float* W1   = (const float*)d_in[10];
    const float* b1   = (const float*)d_in[11];
    const float* W2   = (const float*)d_in[12];
    const float* b2   = (const float*)d_in[13];
    float* out = (float*)d_out;

    // CSR build (depends only on edge_index)
    zero_cnt_kernel<<<(T_WIN * N_NODES + 255) / 256, 256>>>();
    count_kernel<<<(T_WIN * E_PER_T + 255) / 256, 256>>>(ei);
    scan_kernel<<<T_WIN, 1024>>>();
    fill_kernel<<<(T_WIN * E_PER_T + 255) / 256, 256>>>(ei);

    // QKV projections
    qkv_kernel<<<dim3((M_ROWS + 63) / 64, 3), 256>>>(x, Wq, bq, Wk, bk, Wv, bv);

    // Gather-aggregate
    agg_kernel<<<dim3((N_NODES * 32 + 255) / 256, T_WIN), 256>>>(x);

    // Dual FFN (8 warps x 4 nodes per block)
    ffn_kernel<<<(TN / 4 + 7) / 8, 256>>>(ln_s, ln_b, W1, b1, W2, b2, out);
}